// round 7
// baseline (speedup 1.0000x reference)
#include <cuda_runtime.h>
#include <cuda_bf16.h>
#include <cstdint>
#include <math.h>

#define NN    4096
#define IN_F  256
#define H     8
#define D     64
#define HD    (H * D)          // 512
#define INV_SCALE 0.25f        // 1 / (8.0 * 0.5)

// ---------------------------------------------------------------------------
// Scratch (__device__ globals: allocation-free rule)
// ---------------------------------------------------------------------------
__device__ __align__(128) __nv_bfloat16 g_Qhi[NN * HD];
__device__ __align__(128) __nv_bfloat16 g_Qlo[NN * HD];
__device__ __align__(128) __nv_bfloat16 g_Khi[NN * HD];
__device__ __align__(128) __nv_bfloat16 g_Klo[NN * HD];
__device__ __align__(128) float g_Zp[(size_t)H * NN * 32];   // per-(h,n) partial sums over 32 m-tiles
__device__ __align__(128) float g_Zinv[(size_t)H * NN];      // 1 / rowsum

// ---------------------------------------------------------------------------
// Warp MMA helpers (sm_80+ path — tcgen05 unavailable on compute_100 target)
// ---------------------------------------------------------------------------
__device__ __forceinline__ uint32_t smem_u32(const void* p) {
    uint32_t a;
    asm("{ .reg .u64 t; cvta.to.shared.u64 t, %1; cvt.u32.u64 %0, t; }"
        : "=r"(a) : "l"(p));
    return a;
}

__device__ __forceinline__ void ldsm_x4(uint32_t (&r)[4], uint32_t addr) {
    asm volatile("ldmatrix.sync.aligned.m8n8.x4.shared.b16 {%0,%1,%2,%3}, [%4];"
                 : "=r"(r[0]), "=r"(r[1]), "=r"(r[2]), "=r"(r[3]) : "r"(addr));
}

__device__ __forceinline__ void mma16816(float (&d)[4], const uint32_t (&a)[4],
                                         uint32_t b0, uint32_t b1) {
    asm volatile(
        "mma.sync.aligned.m16n8k16.row.col.f32.bf16.bf16.f32 "
        "{%0,%1,%2,%3}, {%4,%5,%6,%7}, {%8,%9}, {%0,%1,%2,%3};"
        : "+f"(d[0]), "+f"(d[1]), "+f"(d[2]), "+f"(d[3])
        : "r"(a[0]), "r"(a[1]), "r"(a[2]), "r"(a[3]), "r"(b0), "r"(b1));
}

#define CP_ASYNC16(dst, src) \
    asm volatile("cp.async.cg.shared.global [%0], [%1], 16;" \
                 :: "r"(dst), "l"(src) : "memory")
#define CP_COMMIT()  asm volatile("cp.async.commit_group;" ::: "memory")
#define CP_WAIT0()   asm volatile("cp.async.wait_group 0;" ::: "memory")

// smem tile layout (per buffer): 4 tiles of 128 rows x 128B
#define A_HI 0
#define A_LO 16384
#define B_HI 32768
#define B_LO 49152
#define TILESET 65536

// ---------------------------------------------------------------------------
// Kernel 1: Q/K projection (fp32 CUDA cores), epilogue splits to bf16 hi/lo.
// ---------------------------------------------------------------------------
__global__ void proj_kernel(const float* __restrict__ X,
                            const float* __restrict__ Wq, const float* __restrict__ bq,
                            const float* __restrict__ Wk, const float* __restrict__ bk)
{
    const float* W = (blockIdx.z == 0) ? Wq : Wk;
    const float* b = (blockIdx.z == 0) ? bq : bk;
    __nv_bfloat16* Ohi = (blockIdx.z == 0) ? g_Qhi : g_Khi;
    __nv_bfloat16* Olo = (blockIdx.z == 0) ? g_Qlo : g_Klo;

    __shared__ float As[16][68];
    __shared__ float Bs[16][68];

    const int tid  = threadIdx.x;
    const int row0 = blockIdx.y * 64;
    const int col0 = blockIdx.x * 64;
    const int tx   = tid & 15;
    const int ty   = tid >> 4;

    float acc[4][4] = {};

    for (int k0 = 0; k0 < IN_F; k0 += 16) {
        #pragma unroll
        for (int l = 0; l < 4; l++) {
            int e = tid + l * 256;
            int k = e & 15, i = e >> 4;
            As[k][i] = X[(row0 + i) * IN_F + k0 + k];
        }
        #pragma unroll
        for (int l = 0; l < 4; l++) {
            int e = tid + l * 256;
            int j = e & 63, k = e >> 6;
            Bs[k][j] = W[(k0 + k) * HD + col0 + j];
        }
        __syncthreads();
        #pragma unroll
        for (int k = 0; k < 16; k++) {
            float a[4], bb[4];
            #pragma unroll
            for (int i = 0; i < 4; i++) a[i]  = As[k][ty * 4 + i];
            #pragma unroll
            for (int j = 0; j < 4; j++) bb[j] = Bs[k][tx * 4 + j];
            #pragma unroll
            for (int i = 0; i < 4; i++)
                #pragma unroll
                for (int j = 0; j < 4; j++)
                    acc[i][j] = fmaf(a[i], bb[j], acc[i][j]);
        }
        __syncthreads();
    }

    #pragma unroll
    for (int i = 0; i < 4; i++) {
        int r = row0 + ty * 4 + i;
        #pragma unroll
        for (int j = 0; j < 4; j++) {
            int c = col0 + tx * 4 + j;
            float v = acc[i][j] + b[c];
            __nv_bfloat16 hi = __float2bfloat16(v);
            __nv_bfloat16 lo = __float2bfloat16(v - __bfloat162float(hi));
            Ohi[r * HD + c] = hi;
            Olo[r * HD + c] = lo;
        }
    }
}

// ---------------------------------------------------------------------------
// Kernel 2: row sums of exp(scores).  Grid (32 m-tiles, 32 n-tiles, 8 heads).
// Identical MMA body to the validated R3 scores kernel; epilogue computes
// per-row partial sums of exp(s) and writes g_Zp (4 MB) — no S store.
// ---------------------------------------------------------------------------
__global__ void __launch_bounds__(256)
sums_kernel()
{
    extern __shared__ char sm[];
    const uint32_t smb = smem_u32(sm);
    __shared__ float s_part[128][4];

    const int tid  = threadIdx.x;
    const int wid  = tid >> 5;
    const int lane = tid & 31;

    const int h  = blockIdx.z;
    const int bm = blockIdx.x;
    const int m0 = bm * 128;
    const int n0 = blockIdx.y * 128;

    #pragma unroll
    for (int it = 0; it < 4; it++) {
        int e   = tid + it * 256;
        int row = e >> 3;
        int c   = e & 7;
        uint32_t dstoff = (uint32_t)(row * 128 + ((c ^ (row & 7)) * 16));
        size_t gq = (size_t)(n0 + row) * HD + h * D + c * 8;
        size_t gk = (size_t)(m0 + row) * HD + h * D + c * 8;
        *reinterpret_cast<uint4*>(sm + A_HI + dstoff) =
            *reinterpret_cast<const uint4*>(g_Qhi + gq);
        *reinterpret_cast<uint4*>(sm + A_LO + dstoff) =
            *reinterpret_cast<const uint4*>(g_Qlo + gq);
        *reinterpret_cast<uint4*>(sm + B_HI + dstoff) =
            *reinterpret_cast<const uint4*>(g_Khi + gk);
        *reinterpret_cast<uint4*>(sm + B_LO + dstoff) =
            *reinterpret_cast<const uint4*>(g_Klo + gk);
    }
    __syncthreads();

    const int m_base = (wid & 1) * 64;
    const int n_base = (wid >> 1) * 32;

    const int xr     = lane & 7;
    const int a_row  = (lane & 7) + ((lane >> 3) & 1) * 8;
    const int a_half = lane >> 4;
    const int b_row  = (lane & 7) + ((lane >> 4) ? 8 : 0);
    const int b_half = (lane >> 3) & 1;

    float acc[4][4][4];
    #pragma unroll
    for (int mi = 0; mi < 4; mi++)
        #pragma unroll
        for (int nj = 0; nj < 4; nj++)
            #pragma unroll
            for (int f = 0; f < 4; f++) acc[mi][nj][f] = 0.0f;

    const uint32_t a_off[3] = {A_HI, A_HI, A_LO};
    const uint32_t b_off[3] = {B_HI, B_LO, B_HI};

    #pragma unroll
    for (int t = 0; t < 3; t++) {
        const uint32_t Ab = smb + a_off[t];
        const uint32_t Bb = smb + b_off[t];
        #pragma unroll
        for (int k = 0; k < 4; k++) {
            uint32_t af[4][4];
            #pragma unroll
            for (int mi = 0; mi < 4; mi++) {
                int row = m_base + mi * 16 + a_row;
                ldsm_x4(af[mi], Ab + row * 128 + (((2 * k + a_half) ^ xr) * 16));
            }
            uint32_t bf[2][4];
            #pragma unroll
            for (int nb = 0; nb < 2; nb++) {
                int row = n_base + nb * 16 + b_row;
                ldsm_x4(bf[nb], Bb + row * 128 + (((2 * k + b_half) ^ xr) * 16));
            }
            #pragma unroll
            for (int mi = 0; mi < 4; mi++) {
                mma16816(acc[mi][0], af[mi], bf[0][0], bf[0][1]);
                mma16816(acc[mi][1], af[mi], bf[0][2], bf[0][3]);
                mma16816(acc[mi][2], af[mi], bf[1][0], bf[1][1]);
                mma16816(acc[mi][3], af[mi], bf[1][2], bf[1][3]);
            }
        }
    }

    // ---- epilogue: exp + per-row partial sums over this CTA's 128 cols
    const int g = lane >> 2;
    #pragma unroll
    for (int mi = 0; mi < 4; mi++) {
        float rs0 = 0.0f, rs1 = 0.0f;
        #pragma unroll
        for (int nj = 0; nj < 4; nj++) {
            rs0 += __expf(acc[mi][nj][0] * INV_SCALE) + __expf(acc[mi][nj][1] * INV_SCALE);
            rs1 += __expf(acc[mi][nj][2] * INV_SCALE) + __expf(acc[mi][nj][3] * INV_SCALE);
        }
        rs0 += __shfl_xor_sync(0xffffffffu, rs0, 1);
        rs0 += __shfl_xor_sync(0xffffffffu, rs0, 2);
        rs1 += __shfl_xor_sync(0xffffffffu, rs1, 1);
        rs1 += __shfl_xor_sync(0xffffffffu, rs1, 2);
        if ((lane & 3) == 0) {
            s_part[m_base + mi * 16 + g][wid >> 1]     = rs0;
            s_part[m_base + mi * 16 + g + 8][wid >> 1] = rs1;
        }
    }
    __syncthreads();
    if (tid < 128) {
        float z = s_part[tid][0] + s_part[tid][1] + s_part[tid][2] + s_part[tid][3];
        g_Zp[((size_t)h * NN + n0 + tid) * 32 + bm] = z;
    }
}

// ---------------------------------------------------------------------------
// Kernel 3: reduce partial sums -> 1/Z  (deterministic fixed-order sum)
// ---------------------------------------------------------------------------
__global__ void zred_kernel()
{
    int i = blockIdx.x * 256 + threadIdx.x;      // over H*NN = 32768
    const float* __restrict__ p = g_Zp + (size_t)i * 32;
    float s = 0.0f;
    #pragma unroll
    for (int j = 0; j < 32; j++) s += p[j];
    g_Zinv[i] = 1.0f / s;
}

// ---------------------------------------------------------------------------
// Kernel 4: output tile.  Grid (32 m-tiles, 32 n-tiles).  Loops all 8 heads,
// recomputes scores (same MMA body), accumulates exp(s)*Zinv, writes out once.
// cp.async double-buffered head tiles (2 x 64 KB dynamic smem).
// ---------------------------------------------------------------------------
__device__ __forceinline__ void load_head_tiles(uint32_t sbase, int h, int n0,
                                                int m0, int tid)
{
    #pragma unroll
    for (int it = 0; it < 4; it++) {
        int e   = tid + it * 256;
        int row = e >> 3;
        int c   = e & 7;
        uint32_t dstoff = (uint32_t)(row * 128 + ((c ^ (row & 7)) * 16));
        size_t gq = (size_t)(n0 + row) * HD + h * D + c * 8;
        size_t gk = (size_t)(m0 + row) * HD + h * D + c * 8;
        CP_ASYNC16(sbase + A_HI + dstoff, (const void*)(g_Qhi + gq));
        CP_ASYNC16(sbase + A_LO + dstoff, (const void*)(g_Qlo + gq));
        CP_ASYNC16(sbase + B_HI + dstoff, (const void*)(g_Khi + gk));
        CP_ASYNC16(sbase + B_LO + dstoff, (const void*)(g_Klo + gk));
    }
}

__global__ void __launch_bounds__(256)
out_kernel(float* __restrict__ out)
{
    extern __shared__ char sm[];
    const uint32_t smb = smem_u32(sm);
    __shared__ float s_zinv[H * 128];

    const int tid  = threadIdx.x;
    const int wid  = tid >> 5;
    const int lane = tid & 31;

    const int m0 = blockIdx.x * 128;
    const int n0 = blockIdx.y * 128;

    // preload zinv for this CTA's 128 query rows, all heads
    #pragma unroll
    for (int l = 0; l < 4; l++) {
        int e = tid + l * 256;             // 0..1023 = h*128 + r
        s_zinv[e] = g_Zinv[(size_t)(e >> 7) * NN + n0 + (e & 127)];
    }

    load_head_tiles(smb, 0, n0, m0, tid);
    CP_COMMIT();

    const int m_base = (wid & 1) * 64;
    const int n_base = (wid >> 1) * 32;

    const int xr     = lane & 7;
    const int a_row  = (lane & 7) + ((lane >> 3) & 1) * 8;
    const int a_half = lane >> 4;
    const int b_row  = (lane & 7) + ((lane >> 4) ? 8 : 0);
    const int b_half = (lane >> 3) & 1;
    const int g      = lane >> 2;
    const int q      = lane & 3;

    float acc_out[4][4][4];
    #pragma unroll
    for (int mi = 0; mi < 4; mi++)
        #pragma unroll
        for (int nj = 0; nj < 4; nj++)
            #pragma unroll
            for (int f = 0; f < 4; f++) acc_out[mi][nj][f] = 0.0f;

    const uint32_t a_off[3] = {A_HI, A_HI, A_LO};
    const uint32_t b_off[3] = {B_HI, B_LO, B_HI};

    for (int h = 0; h < H; h++) {
        CP_WAIT0();
        __syncthreads();
        if (h < H - 1) {
            load_head_tiles(smb + ((h + 1) & 1) * TILESET, h + 1, n0, m0, tid);
            CP_COMMIT();
        }
        const uint32_t buf = smb + (h & 1) * TILESET;

        float acc[4][4][4];
        #pragma unroll
        for (int mi = 0; mi < 4; mi++)
            #pragma unroll
            for (int nj = 0; nj < 4; nj++)
                #pragma unroll
                for (int f = 0; f < 4; f++) acc[mi][nj][f] = 0.0f;

        #pragma unroll
        for (int t = 0; t < 3; t++) {
            const uint32_t Ab = buf + a_off[t];
            const uint32_t Bb = buf + b_off[t];
            #pragma unroll
            for (int k = 0; k < 4; k++) {
                uint32_t af[4][4];
                #pragma unroll
                for (int mi = 0; mi < 4; mi++) {
                    int row = m_base + mi * 16 + a_row;
                    ldsm_x4(af[mi], Ab + row * 128 + (((2 * k + a_half) ^ xr) * 16));
                }
                uint32_t bf[2][4];
                #pragma unroll
                for (int nb = 0; nb < 2; nb++) {
                    int row = n_base + nb * 16 + b_row;
                    ldsm_x4(bf[nb], Bb + row * 128 + (((2 * k + b_half) ^ xr) * 16));
                }
                #pragma unroll
                for (int mi = 0; mi < 4; mi++) {
                    mma16816(acc[mi][0], af[mi], bf[0][0], bf[0][1]);
                    mma16816(acc[mi][1], af[mi], bf[0][2], bf[0][3]);
                    mma16816(acc[mi][2], af[mi], bf[1][0], bf[1][1]);
                    mma16816(acc[mi][3], af[mi], bf[1][2], bf[1][3]);
                }
            }
        }

        // accumulate softmax numerators * 1/Z for this head
        #pragma unroll
        for (int mi = 0; mi < 4; mi++) {
            float z0 = s_zinv[h * 128 + m_base + mi * 16 + g];
            float z1 = s_zinv[h * 128 + m_base + mi * 16 + g + 8];
            #pragma unroll
            for (int nj = 0; nj < 4; nj++) {
                acc_out[mi][nj][0] += __expf(acc[mi][nj][0] * INV_SCALE) * z0;
                acc_out[mi][nj][1] += __expf(acc[mi][nj][1] * INV_SCALE) * z0;
                acc_out[mi][nj][2] += __expf(acc[mi][nj][2] * INV_SCALE) * z1;
                acc_out[mi][nj][3] += __expf(acc[mi][nj][3] * INV_SCALE) * z1;
            }
        }
        __syncthreads();   // all warps done with buf before its cp.async reuse
    }

    // ---- final store: mean over heads
    const float invH = 1.0f / (float)H;
    #pragma unroll
    for (int mi = 0; mi < 4; mi++) {
        int r0 = n0 + m_base + mi * 16 + g;
        float* __restrict__ p0 = out + (size_t)r0 * NN;
        float* __restrict__ p1 = out + (size_t)(r0 + 8) * NN;
        #pragma unroll
        for (int nj = 0; nj < 4; nj++) {
            int c = m0 + n_base + nj * 8 + 2 * q;
            float2 v0 = make_float2(acc_out[mi][nj][0] * invH, acc_out[mi][nj][1] * invH);
            float2 v1 = make_float2(acc_out[mi][nj][2] * invH, acc_out[mi][nj][3] * invH);
            *reinterpret_cast<float2*>(p0 + c) = v0;
            *reinterpret_cast<float2*>(p1 + c) = v1;
        }
    }
}

// ---------------------------------------------------------------------------
extern "C" void kernel_launch(void* const* d_in, const int* in_sizes, int n_in,
                              void* d_out, int out_size)
{
    const float* X  = (const float*)d_in[0];
    const float* Wq = (const float*)d_in[1];
    const float* bq = (const float*)d_in[2];
    const float* Wk = (const float*)d_in[3];
    const float* bk = (const float*)d_in[4];
    float* out = (float*)d_out;

    (void)in_sizes; (void)n_in; (void)out_size;

    cudaFuncSetAttribute(sums_kernel,
                         cudaFuncAttributeMaxDynamicSharedMemorySize, TILESET);
    cudaFuncSetAttribute(out_kernel,
                         cudaFuncAttributeMaxDynamicSharedMemorySize, 2 * TILESET);

    {
        dim3 grid(HD / 64, NN / 64, 2);
        proj_kernel<<<grid, 256>>>(X, Wq, bq, Wk, bk);
    }
    {
        dim3 grid(NN / 128, NN / 128, H);
        sums_kernel<<<grid, 256, TILESET>>>();
    }
    zred_kernel<<<(H * NN) / 256, 256>>>();
    {
        dim3 grid(NN / 128, NN / 128);
        out_kernel<<<grid, 256, 2 * TILESET>>>(out);
    }
}

// round 8
// speedup vs baseline: 1.1040x; 1.1040x over previous
#include <cuda_runtime.h>
#include <cuda_bf16.h>
#include <cuda_fp16.h>
#include <cstdint>
#include <math.h>

#define NN    4096
#define IN_F  256
#define H     8
#define D     64
#define HD    (H * D)          // 512
#define INV_SCALE 0.25f        // 1 / (8.0 * 0.5)

// ---------------------------------------------------------------------------
// Scratch (__device__ globals: allocation-free rule)
// ---------------------------------------------------------------------------
__device__ __align__(128) __nv_bfloat16 g_Qhi[NN * HD];
__device__ __align__(128) __nv_bfloat16 g_Qlo[NN * HD];
__device__ __align__(128) __nv_bfloat16 g_Khi[NN * HD];
__device__ __align__(128) __nv_bfloat16 g_Klo[NN * HD];
__device__ __align__(128) __half g_U[(size_t)H * NN * NN];   // 256 MB exp(scores) fp16
__device__ __align__(128) float g_Zp[(size_t)H * NN * 32];   // per-(h,n) partial sums over 32 m-tiles
__device__ __align__(128) float g_Zinv[(size_t)H * NN];      // 1 / rowsum

// ---------------------------------------------------------------------------
// Warp MMA helpers (sm_80+ path — tcgen05 unavailable on compute_100 target)
// ---------------------------------------------------------------------------
__device__ __forceinline__ uint32_t smem_u32(const void* p) {
    uint32_t a;
    asm("{ .reg .u64 t; cvta.to.shared.u64 t, %1; cvt.u32.u64 %0, t; }"
        : "=r"(a) : "l"(p));
    return a;
}

__device__ __forceinline__ void ldsm_x4(uint32_t (&r)[4], uint32_t addr) {
    asm volatile("ldmatrix.sync.aligned.m8n8.x4.shared.b16 {%0,%1,%2,%3}, [%4];"
                 : "=r"(r[0]), "=r"(r[1]), "=r"(r[2]), "=r"(r[3]) : "r"(addr));
}

__device__ __forceinline__ void mma16816(float (&d)[4], const uint32_t (&a)[4],
                                         uint32_t b0, uint32_t b1) {
    asm volatile(
        "mma.sync.aligned.m16n8k16.row.col.f32.bf16.bf16.f32 "
        "{%0,%1,%2,%3}, {%4,%5,%6,%7}, {%8,%9}, {%0,%1,%2,%3};"
        : "+f"(d[0]), "+f"(d[1]), "+f"(d[2]), "+f"(d[3])
        : "r"(a[0]), "r"(a[1]), "r"(a[2]), "r"(a[3]), "r"(b0), "r"(b1));
}

// smem tile layout: 4 tiles of 128 rows x 128B
#define A_HI 0
#define A_LO 16384
#define B_HI 32768
#define B_LO 49152
#define TILESET 65536

// ---------------------------------------------------------------------------
// Kernel 1: Q/K projection (fp32 CUDA cores), epilogue splits to bf16 hi/lo.
// ---------------------------------------------------------------------------
__global__ void proj_kernel(const float* __restrict__ X,
                            const float* __restrict__ Wq, const float* __restrict__ bq,
                            const float* __restrict__ Wk, const float* __restrict__ bk)
{
    const float* W = (blockIdx.z == 0) ? Wq : Wk;
    const float* b = (blockIdx.z == 0) ? bq : bk;
    __nv_bfloat16* Ohi = (blockIdx.z == 0) ? g_Qhi : g_Khi;
    __nv_bfloat16* Olo = (blockIdx.z == 0) ? g_Qlo : g_Klo;

    __shared__ float As[16][68];
    __shared__ float Bs[16][68];

    const int tid  = threadIdx.x;
    const int row0 = blockIdx.y * 64;
    const int col0 = blockIdx.x * 64;
    const int tx   = tid & 15;
    const int ty   = tid >> 4;

    float acc[4][4] = {};

    for (int k0 = 0; k0 < IN_F; k0 += 16) {
        #pragma unroll
        for (int l = 0; l < 4; l++) {
            int e = tid + l * 256;
            int k = e & 15, i = e >> 4;
            As[k][i] = X[(row0 + i) * IN_F + k0 + k];
        }
        #pragma unroll
        for (int l = 0; l < 4; l++) {
            int e = tid + l * 256;
            int j = e & 63, k = e >> 6;
            Bs[k][j] = W[(k0 + k) * HD + col0 + j];
        }
        __syncthreads();
        #pragma unroll
        for (int k = 0; k < 16; k++) {
            float a[4], bb[4];
            #pragma unroll
            for (int i = 0; i < 4; i++) a[i]  = As[k][ty * 4 + i];
            #pragma unroll
            for (int j = 0; j < 4; j++) bb[j] = Bs[k][tx * 4 + j];
            #pragma unroll
            for (int i = 0; i < 4; i++)
                #pragma unroll
                for (int j = 0; j < 4; j++)
                    acc[i][j] = fmaf(a[i], bb[j], acc[i][j]);
        }
        __syncthreads();
    }

    #pragma unroll
    for (int i = 0; i < 4; i++) {
        int r = row0 + ty * 4 + i;
        #pragma unroll
        for (int j = 0; j < 4; j++) {
            int c = col0 + tx * 4 + j;
            float v = acc[i][j] + b[c];
            __nv_bfloat16 hi = __float2bfloat16(v);
            __nv_bfloat16 lo = __float2bfloat16(v - __bfloat162float(hi));
            Ohi[r * HD + c] = hi;
            Olo[r * HD + c] = lo;
        }
    }
}

// ---------------------------------------------------------------------------
// Kernel 2: scores pass.  Grid (32 m-tiles, 32 n-tiles, 8 heads).
// Validated R7 sums_kernel MMA body; epilogue computes exp(s), stores U (fp16)
// AND the per-tile row partial sums (validated) — single tensor pass total.
// ---------------------------------------------------------------------------
__global__ void __launch_bounds__(256)
scores_kernel()
{
    extern __shared__ char sm[];
    const uint32_t smb = smem_u32(sm);
    __shared__ float s_part[128][4];

    const int tid  = threadIdx.x;
    const int wid  = tid >> 5;
    const int lane = tid & 31;

    const int h  = blockIdx.z;
    const int bm = blockIdx.x;
    const int m0 = bm * 128;
    const int n0 = blockIdx.y * 128;

    #pragma unroll
    for (int it = 0; it < 4; it++) {
        int e   = tid + it * 256;
        int row = e >> 3;
        int c   = e & 7;
        uint32_t dstoff = (uint32_t)(row * 128 + ((c ^ (row & 7)) * 16));
        size_t gq = (size_t)(n0 + row) * HD + h * D + c * 8;
        size_t gk = (size_t)(m0 + row) * HD + h * D + c * 8;
        *reinterpret_cast<uint4*>(sm + A_HI + dstoff) =
            *reinterpret_cast<const uint4*>(g_Qhi + gq);
        *reinterpret_cast<uint4*>(sm + A_LO + dstoff) =
            *reinterpret_cast<const uint4*>(g_Qlo + gq);
        *reinterpret_cast<uint4*>(sm + B_HI + dstoff) =
            *reinterpret_cast<const uint4*>(g_Khi + gk);
        *reinterpret_cast<uint4*>(sm + B_LO + dstoff) =
            *reinterpret_cast<const uint4*>(g_Klo + gk);
    }
    __syncthreads();

    const int m_base = (wid & 1) * 64;
    const int n_base = (wid >> 1) * 32;

    const int xr     = lane & 7;
    const int a_row  = (lane & 7) + ((lane >> 3) & 1) * 8;
    const int a_half = lane >> 4;
    const int b_row  = (lane & 7) + ((lane >> 4) ? 8 : 0);
    const int b_half = (lane >> 3) & 1;

    float acc[4][4][4];
    #pragma unroll
    for (int mi = 0; mi < 4; mi++)
        #pragma unroll
        for (int nj = 0; nj < 4; nj++)
            #pragma unroll
            for (int f = 0; f < 4; f++) acc[mi][nj][f] = 0.0f;

    const uint32_t a_off[3] = {A_HI, A_HI, A_LO};
    const uint32_t b_off[3] = {B_HI, B_LO, B_HI};

    #pragma unroll
    for (int t = 0; t < 3; t++) {
        const uint32_t Ab = smb + a_off[t];
        const uint32_t Bb = smb + b_off[t];
        #pragma unroll
        for (int k = 0; k < 4; k++) {
            uint32_t af[4][4];
            #pragma unroll
            for (int mi = 0; mi < 4; mi++) {
                int row = m_base + mi * 16 + a_row;
                ldsm_x4(af[mi], Ab + row * 128 + (((2 * k + a_half) ^ xr) * 16));
            }
            uint32_t bf[2][4];
            #pragma unroll
            for (int nb = 0; nb < 2; nb++) {
                int row = n_base + nb * 16 + b_row;
                ldsm_x4(bf[nb], Bb + row * 128 + (((2 * k + b_half) ^ xr) * 16));
            }
            #pragma unroll
            for (int mi = 0; mi < 4; mi++) {
                mma16816(acc[mi][0], af[mi], bf[0][0], bf[0][1]);
                mma16816(acc[mi][1], af[mi], bf[0][2], bf[0][3]);
                mma16816(acc[mi][2], af[mi], bf[1][0], bf[1][1]);
                mma16816(acc[mi][3], af[mi], bf[1][2], bf[1][3]);
            }
        }
    }

    // ---- epilogue: exp once; store U fp16; row partial sums (validated)
    const int g = lane >> 2;
    const int q = lane & 3;
    #pragma unroll
    for (int mi = 0; mi < 4; mi++) {
        int r0 = n0 + m_base + mi * 16 + g;            // global query row
        __half* __restrict__ u0 = g_U + ((size_t)h * NN + r0) * NN + m0;
        __half* __restrict__ u1 = g_U + ((size_t)h * NN + r0 + 8) * NN + m0;
        float rs0 = 0.0f, rs1 = 0.0f;
        #pragma unroll
        for (int nj = 0; nj < 4; nj++) {
            float e0 = __expf(acc[mi][nj][0] * INV_SCALE);
            float e1 = __expf(acc[mi][nj][1] * INV_SCALE);
            float e2 = __expf(acc[mi][nj][2] * INV_SCALE);
            float e3 = __expf(acc[mi][nj][3] * INV_SCALE);
            rs0 += e0 + e1;
            rs1 += e2 + e3;
            int c = n_base + nj * 8 + 2 * q;
            *reinterpret_cast<__half2*>(u0 + c) = __floats2half2_rn(e0, e1);
            *reinterpret_cast<__half2*>(u1 + c) = __floats2half2_rn(e2, e3);
        }
        rs0 += __shfl_xor_sync(0xffffffffu, rs0, 1);
        rs0 += __shfl_xor_sync(0xffffffffu, rs0, 2);
        rs1 += __shfl_xor_sync(0xffffffffu, rs1, 1);
        rs1 += __shfl_xor_sync(0xffffffffu, rs1, 2);
        if ((lane & 3) == 0) {
            s_part[m_base + mi * 16 + g][wid >> 1]     = rs0;
            s_part[m_base + mi * 16 + g + 8][wid >> 1] = rs1;
        }
    }
    __syncthreads();
    if (tid < 128) {
        float z = s_part[tid][0] + s_part[tid][1] + s_part[tid][2] + s_part[tid][3];
        g_Zp[((size_t)h * NN + n0 + tid) * 32 + bm] = z;
    }
}

// ---------------------------------------------------------------------------
// Kernel 3: reduce partial sums -> 1/Z  (deterministic fixed-order sum)
// ---------------------------------------------------------------------------
__global__ void zred_kernel()
{
    int i = blockIdx.x * 256 + threadIdx.x;      // over H*NN = 32768
    const float* __restrict__ p = g_Zp + (size_t)i * 32;
    float s = 0.0f;
    #pragma unroll
    for (int j = 0; j < 32; j++) s += p[j];
    g_Zinv[i] = 1.0f / s;
}

// ---------------------------------------------------------------------------
// Kernel 4: normalize + mean over heads (pure streaming).
// out[n][m] = (1/H) * sum_h U[h][n][m] * Zinv[h][n]
// One block per row n; each thread 16 consecutive columns (uint4-vectorized).
// ---------------------------------------------------------------------------
__global__ void __launch_bounds__(256)
norm_kernel(float* __restrict__ out)
{
    const int n   = blockIdx.x;
    const int tid = threadIdx.x;
    __shared__ float zin[H];

    if (tid < H) zin[tid] = g_Zinv[(size_t)tid * NN + n] * (1.0f / (float)H);
    __syncthreads();

    const int c0 = tid * 16;
    float acc[16];
    #pragma unroll
    for (int j = 0; j < 16; j++) acc[j] = 0.0f;

    #pragma unroll
    for (int h = 0; h < H; h++) {
        const uint4* __restrict__ p =
            reinterpret_cast<const uint4*>(g_U + ((size_t)h * NN + n) * NN + c0);
        const float z = zin[h];
        #pragma unroll
        for (int v = 0; v < 2; v++) {
            uint4 raw = p[v];
            const __half2* h2 = reinterpret_cast<const __half2*>(&raw);
            #pragma unroll
            for (int j = 0; j < 4; j++) {
                float2 f = __half22float2(h2[j]);
                acc[v * 8 + j * 2 + 0] = fmaf(f.x, z, acc[v * 8 + j * 2 + 0]);
                acc[v * 8 + j * 2 + 1] = fmaf(f.y, z, acc[v * 8 + j * 2 + 1]);
            }
        }
    }

    float* __restrict__ dst = out + (size_t)n * NN + c0;
    #pragma unroll
    for (int v = 0; v < 4; v++) {
        float4 w = make_float4(acc[v * 4 + 0], acc[v * 4 + 1],
                               acc[v * 4 + 2], acc[v * 4 + 3]);
        reinterpret_cast<float4*>(dst)[v] = w;
    }
}

// ---------------------------------------------------------------------------
extern "C" void kernel_launch(void* const* d_in, const int* in_sizes, int n_in,
                              void* d_out, int out_size)
{
    const float* X  = (const float*)d_in[0];
    const float* Wq = (const float*)d_in[1];
    const float* bq = (const float*)d_in[2];
    const float* Wk = (const float*)d_in[3];
    const float* bk = (const float*)d_in[4];
    float* out = (float*)d_out;

    (void)in_sizes; (void)n_in; (void)out_size;

    cudaFuncSetAttribute(scores_kernel,
                         cudaFuncAttributeMaxDynamicSharedMemorySize, TILESET);

    {
        dim3 grid(HD / 64, NN / 64, 2);
        proj_kernel<<<grid, 256>>>(X, Wq, bq, Wk, bk);
    }
    {
        dim3 grid(NN / 128, NN / 128, H);
        scores_kernel<<<grid, 256, TILESET>>>();
    }
    zred_kernel<<<(H * NN) / 256, 256>>>();
    norm_kernel<<<NN, 256>>>(out);
}

// round 9
// speedup vs baseline: 1.4881x; 1.3479x over previous
#include <cuda_runtime.h>
#include <cuda_fp16.h>
#include <cstdint>
#include <math.h>

#define NN    4096
#define IN_F  256
#define H     8
#define D     64
#define HD    (H * D)          // 512
#define INV_SCALE 0.25f        // 1 / (8.0 * 0.5)

// ---------------------------------------------------------------------------
// Scratch (__device__ globals: allocation-free rule)
// ---------------------------------------------------------------------------
__device__ __align__(128) __half g_Qhi[NN * HD];
__device__ __align__(128) __half g_Qlo[NN * HD];
__device__ __align__(128) __half g_K[NN * HD];
__device__ __align__(128) __half g_U[(size_t)H * NN * NN];   // 256 MB exp(scores) fp16
__device__ __align__(128) float g_Zp[(size_t)32 * H * NN];   // [bm][h][n] partial sums (transposed)
__device__ __align__(128) float g_Zinv[(size_t)H * NN];      // 1 / rowsum

// ---------------------------------------------------------------------------
// Warp MMA helpers (sm_80+ path — tcgen05 unavailable on compute_100 target)
// ---------------------------------------------------------------------------
__device__ __forceinline__ uint32_t smem_u32(const void* p) {
    uint32_t a;
    asm("{ .reg .u64 t; cvta.to.shared.u64 t, %1; cvt.u32.u64 %0, t; }"
        : "=r"(a) : "l"(p));
    return a;
}

__device__ __forceinline__ void ldsm_x4(uint32_t (&r)[4], uint32_t addr) {
    asm volatile("ldmatrix.sync.aligned.m8n8.x4.shared.b16 {%0,%1,%2,%3}, [%4];"
                 : "=r"(r[0]), "=r"(r[1]), "=r"(r[2]), "=r"(r[3]) : "r"(addr));
}

__device__ __forceinline__ void mma16816(float (&d)[4], const uint32_t (&a)[4],
                                         uint32_t b0, uint32_t b1) {
    asm volatile(
        "mma.sync.aligned.m16n8k16.row.col.f32.f16.f16.f32 "
        "{%0,%1,%2,%3}, {%4,%5,%6,%7}, {%8,%9}, {%0,%1,%2,%3};"
        : "+f"(d[0]), "+f"(d[1]), "+f"(d[2]), "+f"(d[3])
        : "r"(a[0]), "r"(a[1]), "r"(a[2]), "r"(a[3]), "r"(b0), "r"(b1));
}

// smem tile layout: 3 tiles of 128 rows x 128B (Qhi, Qlo, K)
#define A_HI 0
#define A_LO 16384
#define B_T  32768
#define TILESET 49152
// U staging layout (reuses tile smem after MMA): 128 rows x 272B (padded,
// 272/4 = 68 ≡ 4 mod 32 -> rows g..g+7 hit distinct bank groups)
#define U_STRIDE 272

// ---------------------------------------------------------------------------
// Kernel 1: Q/K projection.  Q -> fp16 hi/lo split; K -> single fp16.
// ---------------------------------------------------------------------------
__global__ void proj_kernel(const float* __restrict__ X,
                            const float* __restrict__ Wq, const float* __restrict__ bq,
                            const float* __restrict__ Wk, const float* __restrict__ bk)
{
    const bool isQ = (blockIdx.z == 0);
    const float* W = isQ ? Wq : Wk;
    const float* b = isQ ? bq : bk;

    __shared__ float As[16][68];
    __shared__ float Bs[16][68];

    const int tid  = threadIdx.x;
    const int row0 = blockIdx.y * 64;
    const int col0 = blockIdx.x * 64;
    const int tx   = tid & 15;
    const int ty   = tid >> 4;

    float acc[4][4] = {};

    for (int k0 = 0; k0 < IN_F; k0 += 16) {
        #pragma unroll
        for (int l = 0; l < 4; l++) {
            int e = tid + l * 256;
            int k = e & 15, i = e >> 4;
            As[k][i] = X[(row0 + i) * IN_F + k0 + k];
        }
        #pragma unroll
        for (int l = 0; l < 4; l++) {
            int e = tid + l * 256;
            int j = e & 63, k = e >> 6;
            Bs[k][j] = W[(k0 + k) * HD + col0 + j];
        }
        __syncthreads();
        #pragma unroll
        for (int k = 0; k < 16; k++) {
            float a[4], bb[4];
            #pragma unroll
            for (int i = 0; i < 4; i++) a[i]  = As[k][ty * 4 + i];
            #pragma unroll
            for (int j = 0; j < 4; j++) bb[j] = Bs[k][tx * 4 + j];
            #pragma unroll
            for (int i = 0; i < 4; i++)
                #pragma unroll
                for (int j = 0; j < 4; j++)
                    acc[i][j] = fmaf(a[i], bb[j], acc[i][j]);
        }
        __syncthreads();
    }

    #pragma unroll
    for (int i = 0; i < 4; i++) {
        int r = row0 + ty * 4 + i;
        #pragma unroll
        for (int j = 0; j < 4; j++) {
            int c = col0 + tx * 4 + j;
            float v = acc[i][j] + b[c];
            if (isQ) {
                __half hi = __float2half_rn(v);
                __half lo = __float2half_rn(v - __half2float(hi));
                g_Qhi[r * HD + c] = hi;
                g_Qlo[r * HD + c] = lo;
            } else {
                g_K[r * HD + c] = __float2half_rn(v);
            }
        }
    }
}

// ---------------------------------------------------------------------------
// Kernel 2: scores pass.  Grid (32 m-tiles, 32 n-tiles, 8 heads).
// fp16 2-term MMA (Qhi*K + Qlo*K); epilogue: exp in place, row partial sums
// from registers, then STAGED coalesced fp16 U store via padded smem.
// ---------------------------------------------------------------------------
__global__ void __launch_bounds__(256)
scores_kernel()
{
    extern __shared__ char sm[];
    const uint32_t smb = smem_u32(sm);
    __shared__ float s_part[128][4];

    const int tid  = threadIdx.x;
    const int wid  = tid >> 5;
    const int lane = tid & 31;

    const int h  = blockIdx.z;
    const int bm = blockIdx.x;
    const int m0 = bm * 128;
    const int n0 = blockIdx.y * 128;

    // ---- load 3 tiles (128 rows x 64 fp16 = 16 KB each), swizzled 16B chunks
    #pragma unroll
    for (int it = 0; it < 4; it++) {
        int e   = tid + it * 256;        // 0..1023
        int row = e >> 3;
        int c   = e & 7;
        uint32_t dstoff = (uint32_t)(row * 128 + ((c ^ (row & 7)) * 16));
        size_t gq = (size_t)(n0 + row) * HD + h * D + c * 8;
        size_t gk = (size_t)(m0 + row) * HD + h * D + c * 8;
        *reinterpret_cast<uint4*>(sm + A_HI + dstoff) =
            *reinterpret_cast<const uint4*>(g_Qhi + gq);
        *reinterpret_cast<uint4*>(sm + A_LO + dstoff) =
            *reinterpret_cast<const uint4*>(g_Qlo + gq);
        *reinterpret_cast<uint4*>(sm + B_T + dstoff) =
            *reinterpret_cast<const uint4*>(g_K + gk);
    }
    __syncthreads();

    const int m_base = (wid & 1) * 64;
    const int n_base = (wid >> 1) * 32;

    const int xr     = lane & 7;
    const int a_row  = (lane & 7) + ((lane >> 3) & 1) * 8;
    const int a_half = lane >> 4;
    const int b_row  = (lane & 7) + ((lane >> 4) ? 8 : 0);
    const int b_half = (lane >> 3) & 1;

    float acc[4][4][4];
    #pragma unroll
    for (int mi = 0; mi < 4; mi++)
        #pragma unroll
        for (int nj = 0; nj < 4; nj++)
            #pragma unroll
            for (int f = 0; f < 4; f++) acc[mi][nj][f] = 0.0f;

    // 2 terms: (Qhi, K), (Qlo, K)
    #pragma unroll
    for (int t = 0; t < 2; t++) {
        const uint32_t Ab = smb + (t ? A_LO : A_HI);
        const uint32_t Bb = smb + B_T;
        #pragma unroll
        for (int k = 0; k < 4; k++) {
            uint32_t af[4][4];
            #pragma unroll
            for (int mi = 0; mi < 4; mi++) {
                int row = m_base + mi * 16 + a_row;
                ldsm_x4(af[mi], Ab + row * 128 + (((2 * k + a_half) ^ xr) * 16));
            }
            uint32_t bf[2][4];
            #pragma unroll
            for (int nb = 0; nb < 2; nb++) {
                int row = n_base + nb * 16 + b_row;
                ldsm_x4(bf[nb], Bb + row * 128 + (((2 * k + b_half) ^ xr) * 16));
            }
            #pragma unroll
            for (int mi = 0; mi < 4; mi++) {
                mma16816(acc[mi][0], af[mi], bf[0][0], bf[0][1]);
                mma16816(acc[mi][1], af[mi], bf[0][2], bf[0][3]);
                mma16816(acc[mi][2], af[mi], bf[1][0], bf[1][1]);
                mma16816(acc[mi][3], af[mi], bf[1][2], bf[1][3]);
            }
        }
    }

    // ---- exp in place + row partial sums from registers (validated R8 path)
    const int g = lane >> 2;
    const int q = lane & 3;
    #pragma unroll
    for (int mi = 0; mi < 4; mi++) {
        float rs0 = 0.0f, rs1 = 0.0f;
        #pragma unroll
        for (int nj = 0; nj < 4; nj++) {
            acc[mi][nj][0] = __expf(acc[mi][nj][0] * INV_SCALE);
            acc[mi][nj][1] = __expf(acc[mi][nj][1] * INV_SCALE);
            acc[mi][nj][2] = __expf(acc[mi][nj][2] * INV_SCALE);
            acc[mi][nj][3] = __expf(acc[mi][nj][3] * INV_SCALE);
            rs0 += acc[mi][nj][0] + acc[mi][nj][1];
            rs1 += acc[mi][nj][2] + acc[mi][nj][3];
        }
        rs0 += __shfl_xor_sync(0xffffffffu, rs0, 1);
        rs0 += __shfl_xor_sync(0xffffffffu, rs0, 2);
        rs1 += __shfl_xor_sync(0xffffffffu, rs1, 1);
        rs1 += __shfl_xor_sync(0xffffffffu, rs1, 2);
        if ((lane & 3) == 0) {
            s_part[m_base + mi * 16 + g][wid >> 1]     = rs0;
            s_part[m_base + mi * 16 + g + 8][wid >> 1] = rs1;
        }
    }
    __syncthreads();   // all ldsm done -> tile smem reusable; s_part complete

    // ---- stage U tile into padded smem (conflict-free half2 stores)
    #pragma unroll
    for (int mi = 0; mi < 4; mi++) {
        int r0 = m_base + mi * 16 + g;             // tile-local query row
        #pragma unroll
        for (int nj = 0; nj < 4; nj++) {
            int ch = (n_base >> 1) + nj * 4 + q;   // half2 column index
            *reinterpret_cast<__half2*>(sm + r0 * U_STRIDE + ch * 4) =
                __floats2half2_rn(acc[mi][nj][0], acc[mi][nj][1]);
            *reinterpret_cast<__half2*>(sm + (r0 + 8) * U_STRIDE + ch * 4) =
                __floats2half2_rn(acc[mi][nj][2], acc[mi][nj][3]);
        }
    }

    // g_Zp gather (s_part synced above; transposed layout -> coalesced)
    if (tid < 128) {
        float z = s_part[tid][0] + s_part[tid][1] + s_part[tid][2] + s_part[tid][3];
        g_Zp[(size_t)bm * (H * NN) + h * NN + n0 + tid] = z;
    }
    __syncthreads();   // U staging complete

    // ---- coalesced 16B store-out: warp covers 2 rows x 256B
    #pragma unroll
    for (int it = 0; it < 8; it++) {
        int e   = it * 256 + tid;        // 0..2047
        int row = e >> 4;                // 0..127
        int ck  = e & 15;                // 16B chunk
        uint4 v = *reinterpret_cast<const uint4*>(sm + row * U_STRIDE + ck * 16);
        *reinterpret_cast<uint4*>(
            g_U + ((size_t)h * NN + n0 + row) * NN + m0 + ck * 8) = v;
    }
}

// ---------------------------------------------------------------------------
// Kernel 3: reduce partial sums -> 1/Z  (coalesced, deterministic order)
// ---------------------------------------------------------------------------
__global__ void zred_kernel()
{
    int i = blockIdx.x * 256 + threadIdx.x;      // over H*NN = 32768
    float s = 0.0f;
    #pragma unroll
    for (int j = 0; j < 32; j++) s += g_Zp[(size_t)j * (H * NN) + i];
    g_Zinv[i] = 1.0f / s;
}

// ---------------------------------------------------------------------------
// Kernel 4: normalize + mean over heads (pure streaming; 74% HBM validated).
// out[n][m] = (1/H) * sum_h U[h][n][m] * Zinv[h][n]
// ---------------------------------------------------------------------------
__global__ void __launch_bounds__(256)
norm_kernel(float* __restrict__ out)
{
    const int n   = blockIdx.x;
    const int tid = threadIdx.x;
    __shared__ float zin[H];

    if (tid < H) zin[tid] = g_Zinv[(size_t)tid * NN + n] * (1.0f / (float)H);
    __syncthreads();

    const int c0 = tid * 16;
    float acc[16];
    #pragma unroll
    for (int j = 0; j < 16; j++) acc[j] = 0.0f;

    #pragma unroll
    for (int h = 0; h < H; h++) {
        const uint4* __restrict__ p =
            reinterpret_cast<const uint4*>(g_U + ((size_t)h * NN + n) * NN + c0);
        const float z = zin[h];
        #pragma unroll
        for (int v = 0; v < 2; v++) {
            uint4 raw = p[v];
            const __half2* h2 = reinterpret_cast<const __half2*>(&raw);
            #pragma unroll
            for (int j = 0; j < 4; j++) {
                float2 f = __half22float2(h2[j]);
                acc[v * 8 + j * 2 + 0] = fmaf(f.x, z, acc[v * 8 + j * 2 + 0]);
                acc[v * 8 + j * 2 + 1] = fmaf(f.y, z, acc[v * 8 + j * 2 + 1]);
            }
        }
    }

    float* __restrict__ dst = out + (size_t)n * NN + c0;
    #pragma unroll
    for (int v = 0; v < 4; v++) {
        float4 w = make_float4(acc[v * 4 + 0], acc[v * 4 + 1],
                               acc[v * 4 + 2], acc[v * 4 + 3]);
        reinterpret_cast<float4*>(dst)[v] = w;
    }
}

// ---------------------------------------------------------------------------
extern "C" void kernel_launch(void* const* d_in, const int* in_sizes, int n_in,
                              void* d_out, int out_size)
{
    const float* X  = (const float*)d_in[0];
    const float* Wq = (const float*)d_in[1];
    const float* bq = (const float*)d_in[2];
    const float* Wk = (const float*)d_in[3];
    const float* bk = (const float*)d_in[4];
    float* out = (float*)d_out;

    (void)in_sizes; (void)n_in; (void)out_size;

    cudaFuncSetAttribute(scores_kernel,
                         cudaFuncAttributeMaxDynamicSharedMemorySize, TILESET);

    {
        dim3 grid(HD / 64, NN / 64, 2);
        proj_kernel<<<grid, 256>>>(X, Wq, bq, Wk, bk);
    }
    {
        dim3 grid(NN / 128, NN / 128, H);
        scores_kernel<<<grid, 256, TILESET>>>();
    }
    zred_kernel<<<(H * NN) / 256, 256>>>();
    norm_kernel<<<NN, 256>>>(out);
}

// round 10
// speedup vs baseline: 1.7698x; 1.1894x over previous
#include <cuda_runtime.h>
#include <cuda_fp16.h>
#include <cstdint>
#include <math.h>

#define NN    4096
#define IN_F  256
#define H     8
#define D     64
#define HD    (H * D)          // 512
#define INV_SCALE 0.25f        // 1 / (8.0 * 0.5)

// ---------------------------------------------------------------------------
// Scratch (__device__ globals: allocation-free rule)
// ---------------------------------------------------------------------------
__device__ __align__(128) __half g_Xhi[NN * IN_F];
__device__ __align__(128) __half g_Xlo[NN * IN_F];
__device__ __align__(128) __half g_Wthi[(2 * HD) * IN_F];    // [n][k], n: 0..511 Wq, 512..1023 Wk
__device__ __align__(128) __half g_Wtlo[(2 * HD) * IN_F];
__device__ __align__(128) __half g_Qhi[NN * HD];
__device__ __align__(128) __half g_Qlo[NN * HD];
__device__ __align__(128) __half g_K[NN * HD];
__device__ __align__(128) __half g_U[(size_t)H * NN * NN];   // 256 MB exp(scores) fp16
__device__ __align__(128) float g_Zp[(size_t)32 * H * NN];   // [bm][h][n] partial sums
__device__ __align__(128) float g_Zinv_unused[1];            // (zred folded into norm)

// ---------------------------------------------------------------------------
// Warp MMA helpers (sm_80+ path — tcgen05 unavailable on compute_100 target)
// ---------------------------------------------------------------------------
__device__ __forceinline__ uint32_t smem_u32(const void* p) {
    uint32_t a;
    asm("{ .reg .u64 t; cvta.to.shared.u64 t, %1; cvt.u32.u64 %0, t; }"
        : "=r"(a) : "l"(p));
    return a;
}

__device__ __forceinline__ void ldsm_x4(uint32_t (&r)[4], uint32_t addr) {
    asm volatile("ldmatrix.sync.aligned.m8n8.x4.shared.b16 {%0,%1,%2,%3}, [%4];"
                 : "=r"(r[0]), "=r"(r[1]), "=r"(r[2]), "=r"(r[3]) : "r"(addr));
}

__device__ __forceinline__ void mma16816(float (&d)[4], const uint32_t (&a)[4],
                                         uint32_t b0, uint32_t b1) {
    asm volatile(
        "mma.sync.aligned.m16n8k16.row.col.f32.f16.f16.f32 "
        "{%0,%1,%2,%3}, {%4,%5,%6,%7}, {%8,%9}, {%0,%1,%2,%3};"
        : "+f"(d[0]), "+f"(d[1]), "+f"(d[2]), "+f"(d[3])
        : "r"(a[0]), "r"(a[1]), "r"(a[2]), "r"(a[3]), "r"(b0), "r"(b1));
}

// scores smem: 3 tiles of 128 rows x 128B (Qhi, Qlo, K)
#define A_HI 0
#define A_LO 16384
#define B_T  32768
#define SCORES_SMEM 49152
#define U_STRIDE 272
// projmma smem: 4 tiles of 128 rows x 128B
#define P_AHI 0
#define P_ALO 16384
#define P_BHI 32768
#define P_BLO 49152
#define PROJ_SMEM 65536

// ---------------------------------------------------------------------------
// Kernel 0a: convert X -> fp16 hi/lo
// ---------------------------------------------------------------------------
__global__ void convx_kernel(const float* __restrict__ X)
{
    int i4 = (blockIdx.x * 256 + threadIdx.x) * 4;     // over NN*IN_F
    float4 v = *reinterpret_cast<const float4*>(X + i4);
    __half h0 = __float2half_rn(v.x), h1 = __float2half_rn(v.y);
    __half h2 = __float2half_rn(v.z), h3 = __float2half_rn(v.w);
    *reinterpret_cast<__half2*>(g_Xhi + i4)     = __halves2half2(h0, h1);
    *reinterpret_cast<__half2*>(g_Xhi + i4 + 2) = __halves2half2(h2, h3);
    __half l0 = __float2half_rn(v.x - __half2float(h0));
    __half l1 = __float2half_rn(v.y - __half2float(h1));
    __half l2 = __float2half_rn(v.z - __half2float(h2));
    __half l3 = __float2half_rn(v.w - __half2float(h3));
    *reinterpret_cast<__half2*>(g_Xlo + i4)     = __halves2half2(l0, l1);
    *reinterpret_cast<__half2*>(g_Xlo + i4 + 2) = __halves2half2(l2, l3);
}

// ---------------------------------------------------------------------------
// Kernel 0b: convert + transpose W -> g_Wt [n][k] fp16 hi/lo.
// Block r (0..1023) writes output row r; thread t = k index.
// ---------------------------------------------------------------------------
__global__ void convw_kernel(const float* __restrict__ Wq,
                             const float* __restrict__ Wk)
{
    int r = blockIdx.x;            // output col index (0..1023)
    int k = threadIdx.x;           // 0..255
    float v = (r < HD) ? Wq[k * HD + r] : Wk[k * HD + (r - HD)];
    __half hi = __float2half_rn(v);
    g_Wthi[r * IN_F + k] = hi;
    g_Wtlo[r * IN_F + k] = __float2half_rn(v - __half2float(hi));
}

// ---------------------------------------------------------------------------
// Kernel 1: projection GEMM via HMMA 3-term.
// C[4096 x 1024] = X @ [Wq | Wk] + [bq | bk];  K = 256 in 4 chunks of 64.
// Grid (8 n-tiles, 32 m-tiles), 256 threads, warp tile 64x32.
// Epilogue: Q cols -> hi/lo split; K cols -> single fp16.
// ---------------------------------------------------------------------------
__global__ void __launch_bounds__(256, 2)
projmma_kernel(const float* __restrict__ bq, const float* __restrict__ bk)
{
    extern __shared__ char sm[];
    const uint32_t smb = smem_u32(sm);
    __shared__ float s_bias[128];

    const int tid  = threadIdx.x;
    const int wid  = tid >> 5;
    const int lane = tid & 31;

    const int n0 = blockIdx.x * 128;   // output col tile (0..1023)
    const int m0 = blockIdx.y * 128;   // row tile
    const bool isQ = (n0 < HD);

    if (tid < 128) {
        int gc = n0 + tid;
        s_bias[tid] = isQ ? bq[gc] : bk[gc - HD];
    }

    const int m_base = (wid & 1) * 64;
    const int n_base = (wid >> 1) * 32;
    const int xr     = lane & 7;
    const int a_row  = (lane & 7) + ((lane >> 3) & 1) * 8;
    const int a_half = lane >> 4;
    const int b_row  = (lane & 7) + ((lane >> 4) ? 8 : 0);
    const int b_half = (lane >> 3) & 1;

    float acc[4][4][4];
    #pragma unroll
    for (int mi = 0; mi < 4; mi++)
        #pragma unroll
        for (int nj = 0; nj < 4; nj++)
            #pragma unroll
            for (int f = 0; f < 4; f++) acc[mi][nj][f] = 0.0f;

    for (int kk = 0; kk < 4; kk++) {           // k chunks of 64
        __syncthreads();
        #pragma unroll
        for (int it = 0; it < 4; it++) {
            int e   = tid + it * 256;
            int row = e >> 3;
            int c   = e & 7;
            uint32_t dstoff = (uint32_t)(row * 128 + ((c ^ (row & 7)) * 16));
            size_t gx = (size_t)(m0 + row) * IN_F + kk * 64 + c * 8;
            size_t gw = (size_t)(n0 + row) * IN_F + kk * 64 + c * 8;
            *reinterpret_cast<uint4*>(sm + P_AHI + dstoff) =
                *reinterpret_cast<const uint4*>(g_Xhi + gx);
            *reinterpret_cast<uint4*>(sm + P_ALO + dstoff) =
                *reinterpret_cast<const uint4*>(g_Xlo + gx);
            *reinterpret_cast<uint4*>(sm + P_BHI + dstoff) =
                *reinterpret_cast<const uint4*>(g_Wthi + gw);
            *reinterpret_cast<uint4*>(sm + P_BLO + dstoff) =
                *reinterpret_cast<const uint4*>(g_Wtlo + gw);
        }
        __syncthreads();

        const uint32_t a_off[3] = {P_AHI, P_AHI, P_ALO};
        const uint32_t b_off[3] = {P_BHI, P_BLO, P_BHI};
        #pragma unroll
        for (int t = 0; t < 3; t++) {
            const uint32_t Ab = smb + a_off[t];
            const uint32_t Bb = smb + b_off[t];
            #pragma unroll
            for (int k = 0; k < 4; k++) {
                uint32_t af[4][4];
                #pragma unroll
                for (int mi = 0; mi < 4; mi++) {
                    int row = m_base + mi * 16 + a_row;
                    ldsm_x4(af[mi], Ab + row * 128 + (((2 * k + a_half) ^ xr) * 16));
                }
                uint32_t bf[2][4];
                #pragma unroll
                for (int nb = 0; nb < 2; nb++) {
                    int row = n_base + nb * 16 + b_row;
                    ldsm_x4(bf[nb], Bb + row * 128 + (((2 * k + b_half) ^ xr) * 16));
                }
                #pragma unroll
                for (int mi = 0; mi < 4; mi++) {
                    mma16816(acc[mi][0], af[mi], bf[0][0], bf[0][1]);
                    mma16816(acc[mi][1], af[mi], bf[0][2], bf[0][3]);
                    mma16816(acc[mi][2], af[mi], bf[1][0], bf[1][1]);
                    mma16816(acc[mi][3], af[mi], bf[1][2], bf[1][3]);
                }
            }
        }
    }

    // epilogue: bias + split store (half2 granularity)
    const int g = lane >> 2;
    const int q = lane & 3;
    #pragma unroll
    for (int mi = 0; mi < 4; mi++) {
        #pragma unroll
        for (int half_row = 0; half_row < 2; half_row++) {
            int row = m0 + m_base + mi * 16 + g + half_row * 8;
            #pragma unroll
            for (int nj = 0; nj < 4; nj++) {
                int cl = n_base + nj * 8 + 2 * q;
                float f0 = acc[mi][nj][half_row * 2 + 0] + s_bias[cl];
                float f1 = acc[mi][nj][half_row * 2 + 1] + s_bias[cl + 1];
                if (isQ) {
                    __half h0 = __float2half_rn(f0), h1 = __float2half_rn(f1);
                    __half l0 = __float2half_rn(f0 - __half2float(h0));
                    __half l1 = __float2half_rn(f1 - __half2float(h1));
                    size_t o = (size_t)row * HD + n0 + cl;
                    *reinterpret_cast<__half2*>(g_Qhi + o) = __halves2half2(h0, h1);
                    *reinterpret_cast<__half2*>(g_Qlo + o) = __halves2half2(l0, l1);
                } else {
                    size_t o = (size_t)row * HD + (n0 - HD) + cl;
                    *reinterpret_cast<__half2*>(g_K + o) =
                        __halves2half2(__float2half_rn(f0), __float2half_rn(f1));
                }
            }
        }
    }
}

// ---------------------------------------------------------------------------
// Kernel 2: scores pass (validated R9 body), now 2 CTAs/SM.
// ---------------------------------------------------------------------------
__global__ void __launch_bounds__(256, 2)
scores_kernel()
{
    extern __shared__ char sm[];
    const uint32_t smb = smem_u32(sm);
    __shared__ float s_part[128][4];

    const int tid  = threadIdx.x;
    const int wid  = tid >> 5;
    const int lane = tid & 31;

    const int h  = blockIdx.z;
    const int bm = blockIdx.x;
    const int m0 = bm * 128;
    const int n0 = blockIdx.y * 128;

    #pragma unroll
    for (int it = 0; it < 4; it++) {
        int e   = tid + it * 256;
        int row = e >> 3;
        int c   = e & 7;
        uint32_t dstoff = (uint32_t)(row * 128 + ((c ^ (row & 7)) * 16));
        size_t gq = (size_t)(n0 + row) * HD + h * D + c * 8;
        size_t gk = (size_t)(m0 + row) * HD + h * D + c * 8;
        *reinterpret_cast<uint4*>(sm + A_HI + dstoff) =
            *reinterpret_cast<const uint4*>(g_Qhi + gq);
        *reinterpret_cast<uint4*>(sm + A_LO + dstoff) =
            *reinterpret_cast<const uint4*>(g_Qlo + gq);
        *reinterpret_cast<uint4*>(sm + B_T + dstoff) =
            *reinterpret_cast<const uint4*>(g_K + gk);
    }
    __syncthreads();

    const int m_base = (wid & 1) * 64;
    const int n_base = (wid >> 1) * 32;
    const int xr     = lane & 7;
    const int a_row  = (lane & 7) + ((lane >> 3) & 1) * 8;
    const int a_half = lane >> 4;
    const int b_row  = (lane & 7) + ((lane >> 4) ? 8 : 0);
    const int b_half = (lane >> 3) & 1;

    float acc[4][4][4];
    #pragma unroll
    for (int mi = 0; mi < 4; mi++)
        #pragma unroll
        for (int nj = 0; nj < 4; nj++)
            #pragma unroll
            for (int f = 0; f < 4; f++) acc[mi][nj][f] = 0.0f;

    #pragma unroll
    for (int t = 0; t < 2; t++) {
        const uint32_t Ab = smb + (t ? A_LO : A_HI);
        const uint32_t Bb = smb + B_T;
        #pragma unroll
        for (int k = 0; k < 4; k++) {
            uint32_t af[4][4];
            #pragma unroll
            for (int mi = 0; mi < 4; mi++) {
                int row = m_base + mi * 16 + a_row;
                ldsm_x4(af[mi], Ab + row * 128 + (((2 * k + a_half) ^ xr) * 16));
            }
            uint32_t bf[2][4];
            #pragma unroll
            for (int nb = 0; nb < 2; nb++) {
                int row = n_base + nb * 16 + b_row;
                ldsm_x4(bf[nb], Bb + row * 128 + (((2 * k + b_half) ^ xr) * 16));
            }
            #pragma unroll
            for (int mi = 0; mi < 4; mi++) {
                mma16816(acc[mi][0], af[mi], bf[0][0], bf[0][1]);
                mma16816(acc[mi][1], af[mi], bf[0][2], bf[0][3]);
                mma16816(acc[mi][2], af[mi], bf[1][0], bf[1][1]);
                mma16816(acc[mi][3], af[mi], bf[1][2], bf[1][3]);
            }
        }
    }

    const int g = lane >> 2;
    const int q = lane & 3;
    #pragma unroll
    for (int mi = 0; mi < 4; mi++) {
        float rs0 = 0.0f, rs1 = 0.0f;
        #pragma unroll
        for (int nj = 0; nj < 4; nj++) {
            acc[mi][nj][0] = __expf(acc[mi][nj][0] * INV_SCALE);
            acc[mi][nj][1] = __expf(acc[mi][nj][1] * INV_SCALE);
            acc[mi][nj][2] = __expf(acc[mi][nj][2] * INV_SCALE);
            acc[mi][nj][3] = __expf(acc[mi][nj][3] * INV_SCALE);
            rs0 += acc[mi][nj][0] + acc[mi][nj][1];
            rs1 += acc[mi][nj][2] + acc[mi][nj][3];
        }
        rs0 += __shfl_xor_sync(0xffffffffu, rs0, 1);
        rs0 += __shfl_xor_sync(0xffffffffu, rs0, 2);
        rs1 += __shfl_xor_sync(0xffffffffu, rs1, 1);
        rs1 += __shfl_xor_sync(0xffffffffu, rs1, 2);
        if ((lane & 3) == 0) {
            s_part[m_base + mi * 16 + g][wid >> 1]     = rs0;
            s_part[m_base + mi * 16 + g + 8][wid >> 1] = rs1;
        }
    }
    __syncthreads();

    #pragma unroll
    for (int mi = 0; mi < 4; mi++) {
        int r0 = m_base + mi * 16 + g;
        #pragma unroll
        for (int nj = 0; nj < 4; nj++) {
            int ch = (n_base >> 1) + nj * 4 + q;
            *reinterpret_cast<__half2*>(sm + r0 * U_STRIDE + ch * 4) =
                __floats2half2_rn(acc[mi][nj][0], acc[mi][nj][1]);
            *reinterpret_cast<__half2*>(sm + (r0 + 8) * U_STRIDE + ch * 4) =
                __floats2half2_rn(acc[mi][nj][2], acc[mi][nj][3]);
        }
    }
    if (tid < 128) {
        float z = s_part[tid][0] + s_part[tid][1] + s_part[tid][2] + s_part[tid][3];
        g_Zp[(size_t)bm * (H * NN) + h * NN + n0 + tid] = z;
    }
    __syncthreads();

    #pragma unroll
    for (int it = 0; it < 8; it++) {
        int e   = it * 256 + tid;
        int row = e >> 4;
        int ck  = e & 15;
        uint4 v = *reinterpret_cast<const uint4*>(sm + row * U_STRIDE + ck * 16);
        *reinterpret_cast<uint4*>(
            g_U + ((size_t)h * NN + n0 + row) * NN + m0 + ck * 8) = v;
    }
}

// ---------------------------------------------------------------------------
// Kernel 3: normalize + mean over heads; zred folded in (fixed-order sums).
// ---------------------------------------------------------------------------
__global__ void __launch_bounds__(256)
norm_kernel(float* __restrict__ out)
{
    const int n   = blockIdx.x;
    const int tid = threadIdx.x;
    __shared__ float zin[H];

    if (tid < H) {
        float s = 0.0f;
        #pragma unroll
        for (int j = 0; j < 32; j++)
            s += g_Zp[(size_t)j * (H * NN) + tid * NN + n];
        zin[tid] = (1.0f / s) * (1.0f / (float)H);
    }
    __syncthreads();

    const int c0 = tid * 16;
    float acc[16];
    #pragma unroll
    for (int j = 0; j < 16; j++) acc[j] = 0.0f;

    #pragma unroll
    for (int h = 0; h < H; h++) {
        const uint4* __restrict__ p =
            reinterpret_cast<const uint4*>(g_U + ((size_t)h * NN + n) * NN + c0);
        const float z = zin[h];
        #pragma unroll
        for (int v = 0; v < 2; v++) {
            uint4 raw = p[v];
            const __half2* h2 = reinterpret_cast<const __half2*>(&raw);
            #pragma unroll
            for (int j = 0; j < 4; j++) {
                float2 f = __half22float2(h2[j]);
                acc[v * 8 + j * 2 + 0] = fmaf(f.x, z, acc[v * 8 + j * 2 + 0]);
                acc[v * 8 + j * 2 + 1] = fmaf(f.y, z, acc[v * 8 + j * 2 + 1]);
            }
        }
    }

    float* __restrict__ dst = out + (size_t)n * NN + c0;
    #pragma unroll
    for (int v = 0; v < 4; v++) {
        float4 w = make_float4(acc[v * 4 + 0], acc[v * 4 + 1],
                               acc[v * 4 + 2], acc[v * 4 + 3]);
        reinterpret_cast<float4*>(dst)[v] = w;
    }
}

// ---------------------------------------------------------------------------
extern "C" void kernel_launch(void* const* d_in, const int* in_sizes, int n_in,
                              void* d_out, int out_size)
{
    const float* X  = (const float*)d_in[0];
    const float* Wq = (const float*)d_in[1];
    const float* bq = (const float*)d_in[2];
    const float* Wk = (const float*)d_in[3];
    const float* bk = (const float*)d_in[4];
    float* out = (float*)d_out;

    (void)in_sizes; (void)n_in; (void)out_size;

    cudaFuncSetAttribute(scores_kernel,
                         cudaFuncAttributeMaxDynamicSharedMemorySize, SCORES_SMEM);
    cudaFuncSetAttribute(projmma_kernel,
                         cudaFuncAttributeMaxDynamicSharedMemorySize, PROJ_SMEM);

    convx_kernel<<<(NN * IN_F) / 1024, 256>>>(X);
    convw_kernel<<<2 * HD, 256>>>(Wq, Wk);
    {
        dim3 grid(2 * HD / 128, NN / 128);
        projmma_kernel<<<grid, 256, PROJ_SMEM>>>(bq, bk);
    }
    {
        dim3 grid(NN / 128, NN / 128, H);
        scores_kernel<<<grid, 256, SCORES_SMEM>>>();
    }
    norm_kernel<<<NN, 256>>>(out);
}

// round 12
// speedup vs baseline: 2.0273x; 1.1455x over previous
#include <cuda_runtime.h>
#include <cuda_fp16.h>
#include <cstdint>
#include <math.h>

#define NN    4096
#define IN_F  256
#define H     8
#define D     64
#define HD    (H * D)          // 512
#define INV_SCALE 0.25f        // 1 / (8.0 * 0.5)

// ---------------------------------------------------------------------------
// Scratch (__device__ globals: allocation-free rule)
// ---------------------------------------------------------------------------
__device__ __align__(128) __half g_Xhi[NN * IN_F];
__device__ __align__(128) __half g_Xlo[NN * IN_F];
__device__ __align__(128) __half g_Wthi[(2 * HD) * IN_F];    // [n][k], n: 0..511 Wq, 512..1023 Wk
__device__ __align__(128) __half g_Wtlo[(2 * HD) * IN_F];
__device__ __align__(128) __half g_Q[NN * HD];               // fp16 Q (single precision term)
__device__ __align__(128) __half g_K[NN * HD];
__device__ __align__(128) __half g_U[(size_t)H * NN * NN];   // 256 MB exp(scores) fp16
__device__ __align__(128) float g_Zp[(size_t)32 * H * NN];   // [bm][h][n] partial sums

// ---------------------------------------------------------------------------
// Warp MMA helpers (sm_80+ path — tcgen05 unavailable on compute_100 target)
// ---------------------------------------------------------------------------
__device__ __forceinline__ uint32_t smem_u32(const void* p) {
    uint32_t a;
    asm("{ .reg .u64 t; cvta.to.shared.u64 t, %1; cvt.u32.u64 %0, t; }"
        : "=r"(a) : "l"(p));
    return a;
}

__device__ __forceinline__ void ldsm_x4(uint32_t (&r)[4], uint32_t addr) {
    asm volatile("ldmatrix.sync.aligned.m8n8.x4.shared.b16 {%0,%1,%2,%3}, [%4];"
                 : "=r"(r[0]), "=r"(r[1]), "=r"(r[2]), "=r"(r[3]) : "r"(addr));
}

__device__ __forceinline__ void mma16816(float (&d)[4], const uint32_t (&a)[4],
                                         uint32_t b0, uint32_t b1) {
    asm volatile(
        "mma.sync.aligned.m16n8k16.row.col.f32.f16.f16.f32 "
        "{%0,%1,%2,%3}, {%4,%5,%6,%7}, {%8,%9}, {%0,%1,%2,%3};"
        : "+f"(d[0]), "+f"(d[1]), "+f"(d[2]), "+f"(d[3])
        : "r"(a[0]), "r"(a[1]), "r"(a[2]), "r"(a[3]), "r"(b0), "r"(b1));
}

// scores smem: 2 tiles of 128 rows x 128B (Q, K); U staging reuses the space
#define A_T  0
#define B_T  16384
#define U_STRIDE 272
#define SCORES_SMEM (128 * U_STRIDE)   // 34816 > 32768 tile bytes
// projmma smem: 4 tiles of 128 rows x 128B
#define P_AHI 0
#define P_ALO 16384
#define P_BHI 32768
#define P_BLO 49152
#define PROJ_SMEM 65536

// ---------------------------------------------------------------------------
// Kernel 0a: convert X -> fp16 hi/lo
// ---------------------------------------------------------------------------
__global__ void convx_kernel(const float* __restrict__ X)
{
    int i4 = (blockIdx.x * 256 + threadIdx.x) * 4;     // over NN*IN_F
    float4 v = *reinterpret_cast<const float4*>(X + i4);
    __half h0 = __float2half_rn(v.x), h1 = __float2half_rn(v.y);
    __half h2 = __float2half_rn(v.z), h3 = __float2half_rn(v.w);
    *reinterpret_cast<__half2*>(g_Xhi + i4)     = __halves2half2(h0, h1);
    *reinterpret_cast<__half2*>(g_Xhi + i4 + 2) = __halves2half2(h2, h3);
    __half l0 = __float2half_rn(v.x - __half2float(h0));
    __half l1 = __float2half_rn(v.y - __half2float(h1));
    __half l2 = __float2half_rn(v.z - __half2float(h2));
    __half l3 = __float2half_rn(v.w - __half2float(h3));
    *reinterpret_cast<__half2*>(g_Xlo + i4)     = __halves2half2(l0, l1);
    *reinterpret_cast<__half2*>(g_Xlo + i4 + 2) = __halves2half2(l2, l3);
}

// ---------------------------------------------------------------------------
// Kernel 0b: convert + transpose W -> g_Wt [n][k] fp16 hi/lo.
// ---------------------------------------------------------------------------
__global__ void convw_kernel(const float* __restrict__ Wq,
                             const float* __restrict__ Wk)
{
    int r = blockIdx.x;            // output col index (0..1023)
    int k = threadIdx.x;           // 0..255
    float v = (r < HD) ? Wq[k * HD + r] : Wk[k * HD + (r - HD)];
    __half hi = __float2half_rn(v);
    g_Wthi[r * IN_F + k] = hi;
    g_Wtlo[r * IN_F + k] = __float2half_rn(v - __half2float(hi));
}

// ---------------------------------------------------------------------------
// Kernel 1: projection GEMM via HMMA 3-term (validated R10).
// Epilogue: Q cols and K cols both stored as single fp16.
// ---------------------------------------------------------------------------
__global__ void __launch_bounds__(256, 2)
projmma_kernel(const float* __restrict__ bq, const float* __restrict__ bk)
{
    extern __shared__ char sm[];
    const uint32_t smb = smem_u32(sm);
    __shared__ float s_bias[128];

    const int tid  = threadIdx.x;
    const int wid  = tid >> 5;
    const int lane = tid & 31;

    const int n0 = blockIdx.x * 128;   // output col tile (0..1023)
    const int m0 = blockIdx.y * 128;   // row tile
    const bool isQ = (n0 < HD);

    if (tid < 128) {
        int gc = n0 + tid;
        s_bias[tid] = isQ ? bq[gc] : bk[gc - HD];
    }

    const int m_base = (wid & 1) * 64;
    const int n_base = (wid >> 1) * 32;
    const int xr     = lane & 7;
    const int a_row  = (lane & 7) + ((lane >> 3) & 1) * 8;
    const int a_half = lane >> 4;
    const int b_row  = (lane & 7) + ((lane >> 4) ? 8 : 0);
    const int b_half = (lane >> 3) & 1;

    float acc[4][4][4];
    #pragma unroll
    for (int mi = 0; mi < 4; mi++)
        #pragma unroll
        for (int nj = 0; nj < 4; nj++)
            #pragma unroll
            for (int f = 0; f < 4; f++) acc[mi][nj][f] = 0.0f;

    for (int kk = 0; kk < 4; kk++) {           // k chunks of 64
        __syncthreads();
        #pragma unroll
        for (int it = 0; it < 4; it++) {
            int e   = tid + it * 256;
            int row = e >> 3;
            int c   = e & 7;
            uint32_t dstoff = (uint32_t)(row * 128 + ((c ^ (row & 7)) * 16));
            size_t gx = (size_t)(m0 + row) * IN_F + kk * 64 + c * 8;
            size_t gw = (size_t)(n0 + row) * IN_F + kk * 64 + c * 8;
            *reinterpret_cast<uint4*>(sm + P_AHI + dstoff) =
                *reinterpret_cast<const uint4*>(g_Xhi + gx);
            *reinterpret_cast<uint4*>(sm + P_ALO + dstoff) =
                *reinterpret_cast<const uint4*>(g_Xlo + gx);
            *reinterpret_cast<uint4*>(sm + P_BHI + dstoff) =
                *reinterpret_cast<const uint4*>(g_Wthi + gw);
            *reinterpret_cast<uint4*>(sm + P_BLO + dstoff) =
                *reinterpret_cast<const uint4*>(g_Wtlo + gw);
        }
        __syncthreads();

        const uint32_t a_off[3] = {P_AHI, P_AHI, P_ALO};
        const uint32_t b_off[3] = {P_BHI, P_BLO, P_BHI};
        #pragma unroll
        for (int t = 0; t < 3; t++) {
            const uint32_t Ab = smb + a_off[t];
            const uint32_t Bb = smb + b_off[t];
            #pragma unroll
            for (int k = 0; k < 4; k++) {
                uint32_t af[4][4];
                #pragma unroll
                for (int mi = 0; mi < 4; mi++) {
                    int row = m_base + mi * 16 + a_row;
                    ldsm_x4(af[mi], Ab + row * 128 + (((2 * k + a_half) ^ xr) * 16));
                }
                uint32_t bf[2][4];
                #pragma unroll
                for (int nb = 0; nb < 2; nb++) {
                    int row = n_base + nb * 16 + b_row;
                    ldsm_x4(bf[nb], Bb + row * 128 + (((2 * k + b_half) ^ xr) * 16));
                }
                #pragma unroll
                for (int mi = 0; mi < 4; mi++) {
                    mma16816(acc[mi][0], af[mi], bf[0][0], bf[0][1]);
                    mma16816(acc[mi][1], af[mi], bf[0][2], bf[0][3]);
                    mma16816(acc[mi][2], af[mi], bf[1][0], bf[1][1]);
                    mma16816(acc[mi][3], af[mi], bf[1][2], bf[1][3]);
                }
            }
        }
    }

    // epilogue: bias + fp16 store (half2 granularity)
    const int g = lane >> 2;
    const int q = lane & 3;
    __half* __restrict__ dstbase = isQ ? g_Q : g_K;
    const int coff = isQ ? n0 : (n0 - HD);
    #pragma unroll
    for (int mi = 0; mi < 4; mi++) {
        #pragma unroll
        for (int half_row = 0; half_row < 2; half_row++) {
            int row = m0 + m_base + mi * 16 + g + half_row * 8;
            #pragma unroll
            for (int nj = 0; nj < 4; nj++) {
                int cl = n_base + nj * 8 + 2 * q;
                float f0 = acc[mi][nj][half_row * 2 + 0] + s_bias[cl];
                float f1 = acc[mi][nj][half_row * 2 + 1] + s_bias[cl + 1];
                size_t o = (size_t)row * HD + coff + cl;
                *reinterpret_cast<__half2*>(dstbase + o) =
                    __halves2half2(__float2half_rn(f0), __float2half_rn(f1));
            }
        }
    }
}

// ---------------------------------------------------------------------------
// Kernel 2: scores pass — single-term pure fp16 MMA (Q·K), staged U store.
// Grid (32 m-tiles, 32 n-tiles, 8 heads), 2 CTAs/SM.
// ---------------------------------------------------------------------------
__global__ void __launch_bounds__(256, 2)
scores_kernel()
{
    extern __shared__ char sm[];
    const uint32_t smb = smem_u32(sm);
    __shared__ float s_part[128][4];

    const int tid  = threadIdx.x;
    const int wid  = tid >> 5;
    const int lane = tid & 31;

    const int h  = blockIdx.z;
    const int bm = blockIdx.x;
    const int m0 = bm * 128;
    const int n0 = blockIdx.y * 128;

    // ---- load 2 tiles (128 rows x 64 fp16 = 16 KB each), swizzled 16B chunks
    #pragma unroll
    for (int it = 0; it < 4; it++) {
        int e   = tid + it * 256;        // 0..1023
        int row = e >> 3;
        int c   = e & 7;
        uint32_t dstoff = (uint32_t)(row * 128 + ((c ^ (row & 7)) * 16));
        size_t gq = (size_t)(n0 + row) * HD + h * D + c * 8;
        size_t gk = (size_t)(m0 + row) * HD + h * D + c * 8;
        *reinterpret_cast<uint4*>(sm + A_T + dstoff) =
            *reinterpret_cast<const uint4*>(g_Q + gq);
        *reinterpret_cast<uint4*>(sm + B_T + dstoff) =
            *reinterpret_cast<const uint4*>(g_K + gk);
    }
    __syncthreads();

    const int m_base = (wid & 1) * 64;
    const int n_base = (wid >> 1) * 32;
    const int xr     = lane & 7;
    const int a_row  = (lane & 7) + ((lane >> 3) & 1) * 8;
    const int a_half = lane >> 4;
    const int b_row  = (lane & 7) + ((lane >> 4) ? 8 : 0);
    const int b_half = (lane >> 3) & 1;

    float acc[4][4][4];
    #pragma unroll
    for (int mi = 0; mi < 4; mi++)
        #pragma unroll
        for (int nj = 0; nj < 4; nj++)
            #pragma unroll
            for (int f = 0; f < 4; f++) acc[mi][nj][f] = 0.0f;

    #pragma unroll
    for (int k = 0; k < 4; k++) {
        uint32_t af[4][4];
        #pragma unroll
        for (int mi = 0; mi < 4; mi++) {
            int row = m_base + mi * 16 + a_row;
            ldsm_x4(af[mi], smb + A_T + row * 128 + (((2 * k + a_half) ^ xr) * 16));
        }
        uint32_t bf[2][4];
        #pragma unroll
        for (int nb = 0; nb < 2; nb++) {
            int row = n_base + nb * 16 + b_row;
            ldsm_x4(bf[nb], smb + B_T + row * 128 + (((2 * k + b_half) ^ xr) * 16));
        }
        #pragma unroll
        for (int mi = 0; mi < 4; mi++) {
            mma16816(acc[mi][0], af[mi], bf[0][0], bf[0][1]);
            mma16816(acc[mi][1], af[mi], bf[0][2], bf[0][3]);
            mma16816(acc[mi][2], af[mi], bf[1][0], bf[1][1]);
            mma16816(acc[mi][3], af[mi], bf[1][2], bf[1][3]);
        }
    }

    // ---- exp in place + row partial sums from registers (validated)
    const int g = lane >> 2;
    const int q = lane & 3;
    #pragma unroll
    for (int mi = 0; mi < 4; mi++) {
        float rs0 = 0.0f, rs1 = 0.0f;
        #pragma unroll
        for (int nj = 0; nj < 4; nj++) {
            acc[mi][nj][0] = __expf(acc[mi][nj][0] * INV_SCALE);
            acc[mi][nj][1] = __expf(acc[mi][nj][1] * INV_SCALE);
            acc[mi][nj][2] = __expf(acc[mi][nj][2] * INV_SCALE);
            acc[mi][nj][3] = __expf(acc[mi][nj][3] * INV_SCALE);
            rs0 += acc[mi][nj][0] + acc[mi][nj][1];
            rs1 += acc[mi][nj][2] + acc[mi][nj][3];
        }
        rs0 += __shfl_xor_sync(0xffffffffu, rs0, 1);
        rs0 += __shfl_xor_sync(0xffffffffu, rs0, 2);
        rs1 += __shfl_xor_sync(0xffffffffu, rs1, 1);
        rs1 += __shfl_xor_sync(0xffffffffu, rs1, 2);
        if ((lane & 3) == 0) {
            s_part[m_base + mi * 16 + g][wid >> 1]     = rs0;
            s_part[m_base + mi * 16 + g + 8][wid >> 1] = rs1;
        }
    }
    __syncthreads();   // ldsm done -> tile smem reusable; s_part complete

    // ---- stage U tile into padded smem (conflict-free half2 stores)
    #pragma unroll
    for (int mi = 0; mi < 4; mi++) {
        int r0 = m_base + mi * 16 + g;
        #pragma unroll
        for (int nj = 0; nj < 4; nj++) {
            int ch = (n_base >> 1) + nj * 4 + q;
            *reinterpret_cast<__half2*>(sm + r0 * U_STRIDE + ch * 4) =
                __floats2half2_rn(acc[mi][nj][0], acc[mi][nj][1]);
            *reinterpret_cast<__half2*>(sm + (r0 + 8) * U_STRIDE + ch * 4) =
                __floats2half2_rn(acc[mi][nj][2], acc[mi][nj][3]);
        }
    }
    if (tid < 128) {
        float z = s_part[tid][0] + s_part[tid][1] + s_part[tid][2] + s_part[tid][3];
        g_Zp[(size_t)bm * (H * NN) + h * NN + n0 + tid] = z;
    }
    __syncthreads();   // U staging complete

    // ---- coalesced 16B store-out: warp covers 2 rows x 256B
    #pragma unroll
    for (int it = 0; it < 8; it++) {
        int e   = it * 256 + tid;
        int row = e >> 4;
        int ck  = e & 15;
        uint4 v = *reinterpret_cast<const uint4*>(sm + row * U_STRIDE + ck * 16);
        *reinterpret_cast<uint4*>(
            g_U + ((size_t)h * NN + n0 + row) * NN + m0 + ck * 8) = v;
    }
}

// ---------------------------------------------------------------------------
// Kernel 3: normalize + mean over heads; zred folded in (fixed-order sums).
// ---------------------------------------------------------------------------
__global__ void __launch_bounds__(256)
norm_kernel(float* __restrict__ out)
{
    const int n   = blockIdx.x;
    const int tid = threadIdx.x;
    __shared__ float zin[H];

    if (tid < H) {
        float s = 0.0f;
        #pragma unroll
        for (int j = 0; j < 32; j++)
            s += g_Zp[(size_t)j * (H * NN) + tid * NN + n];
        zin[tid] = (1.0f / s) * (1.0f / (float)H);
    }
    __syncthreads();

    const int c0 = tid * 16;
    float acc[16];
    #pragma unroll
    for (int j = 0; j < 16; j++) acc[j] = 0.0f;

    #pragma unroll
    for (int h = 0; h < H; h++) {
        const uint4* __restrict__ p =
            reinterpret_cast<const uint4*>(g_U + ((size_t)h * NN + n) * NN + c0);
        const float z = zin[h];
        #pragma unroll
        for (int v = 0; v < 2; v++) {
            uint4 raw = p[v];
            const __half2* h2 = reinterpret_cast<const __half2*>(&raw);
            #pragma unroll
            for (int j = 0; j < 4; j++) {
                float2 f = __half22float2(h2[j]);
                acc[v * 8 + j * 2 + 0] = fmaf(f.x, z, acc[v * 8 + j * 2 + 0]);
                acc[v * 8 + j * 2 + 1] = fmaf(f.y, z, acc[v * 8 + j * 2 + 1]);
            }
        }
    }

    float* __restrict__ dst = out + (size_t)n * NN + c0;
    #pragma unroll
    for (int v = 0; v < 4; v++) {
        float4 w = make_float4(acc[v * 4 + 0], acc[v * 4 + 1],
                               acc[v * 4 + 2], acc[v * 4 + 3]);
        reinterpret_cast<float4*>(dst)[v] = w;
    }
}

// ---------------------------------------------------------------------------
extern "C" void kernel_launch(void* const* d_in, const int* in_sizes, int n_in,
                              void* d_out, int out_size)
{
    const float* X  = (const float*)d_in[0];
    const float* Wq = (const float*)d_in[1];
    const float* bq = (const float*)d_in[2];
    const float* Wk = (const float*)d_in[3];
    const float* bk = (const float*)d_in[4];
    float* out = (float*)d_out;

    (void)in_sizes; (void)n_in; (void)out_size;

    cudaFuncSetAttribute(scores_kernel,
                         cudaFuncAttributeMaxDynamicSharedMemorySize, SCORES_SMEM);
    cudaFuncSetAttribute(projmma_kernel,
                         cudaFuncAttributeMaxDynamicSharedMemorySize, PROJ_SMEM);

    convx_kernel<<<(NN * IN_F) / 1024, 256>>>(X);
    convw_kernel<<<2 * HD, 256>>>(Wq, Wk);
    {
        dim3 grid(2 * HD / 128, NN / 128);
        projmma_kernel<<<grid, 256, PROJ_SMEM>>>(bq, bk);
    }
    {
        dim3 grid(NN / 128, NN / 128, H);
        scores_kernel<<<grid, 256, SCORES_SMEM>>>();
    }
    norm_kernel<<<NN, 256>>>(out);
}

// round 15
// speedup vs baseline: 2.1859x; 1.0783x over previous
#include <cuda_runtime.h>
#include <cuda_fp16.h>
#include <cstdint>
#include <math.h>

#define NN    4096
#define IN_F  256
#define H     8
#define D     64
#define HD    (H * D)          // 512
// scores use exp2: fold 0.25 * log2(e) into Q at projection time
#define QSCALE 0.36067376022224085f

// ---------------------------------------------------------------------------
// Scratch (__device__ globals: allocation-free rule)
// ---------------------------------------------------------------------------
__device__ __align__(128) __half g_Xhi[NN * IN_F];
__device__ __align__(128) __half g_Xlo[NN * IN_F];
__device__ __align__(128) __half g_Wthi[(2 * HD) * IN_F];    // [n][k], n: 0..511 Wq, 512..1023 Wk
__device__ __align__(128) __half g_Wtlo[(2 * HD) * IN_F];
__device__ __align__(128) __half g_Q[NN * HD];               // fp16 Q, pre-scaled by QSCALE
__device__ __align__(128) __half g_K[NN * HD];
__device__ __align__(128) __half g_U[(size_t)H * NN * NN];   // 256 MB exp(scores) fp16

// ---------------------------------------------------------------------------
// Warp MMA helpers (sm_80+ path — tcgen05 unavailable on compute_100 target)
// ---------------------------------------------------------------------------
__device__ __forceinline__ uint32_t smem_u32(const void* p) {
    uint32_t a;
    asm("{ .reg .u64 t; cvta.to.shared.u64 t, %1; cvt.u32.u64 %0, t; }"
        : "=r"(a) : "l"(p));
    return a;
}

__device__ __forceinline__ void ldsm_x4(uint32_t (&r)[4], uint32_t addr) {
    asm volatile("ldmatrix.sync.aligned.m8n8.x4.shared.b16 {%0,%1,%2,%3}, [%4];"
                 : "=r"(r[0]), "=r"(r[1]), "=r"(r[2]), "=r"(r[3]) : "r"(addr));
}

__device__ __forceinline__ void mma16816(float (&d)[4], const uint32_t (&a)[4],
                                         uint32_t b0, uint32_t b1) {
    asm volatile(
        "mma.sync.aligned.m16n8k16.row.col.f32.f16.f16.f32 "
        "{%0,%1,%2,%3}, {%4,%5,%6,%7}, {%8,%9}, {%0,%1,%2,%3};"
        : "+f"(d[0]), "+f"(d[1]), "+f"(d[2]), "+f"(d[3])
        : "r"(a[0]), "r"(a[1]), "r"(a[2]), "r"(a[3]), "r"(b0), "r"(b1));
}

__device__ __forceinline__ float ex2f(float x) {
    float y;
    asm("ex2.approx.ftz.f32 %0, %1;" : "=f"(y) : "f"(x));
    return y;
}

// scores smem: 2 tiles of 128 rows x 128B (Q, K); U staging reuses the space
#define A_T  0
#define B_T  16384
#define U_STRIDE 272
#define SCORES_SMEM (128 * U_STRIDE)   // 34816 > 32768 tile bytes
// projmma smem: 4 tiles of 128 rows x 128B
#define P_AHI 0
#define P_ALO 16384
#define P_BHI 32768
#define P_BLO 49152
#define PROJ_SMEM 65536

// ---------------------------------------------------------------------------
// Kernel 0a: convert X -> fp16 hi/lo
// ---------------------------------------------------------------------------
__global__ void convx_kernel(const float* __restrict__ X)
{
    int i4 = (blockIdx.x * 256 + threadIdx.x) * 4;     // over NN*IN_F
    float4 v = *reinterpret_cast<const float4*>(X + i4);
    __half h0 = __float2half_rn(v.x), h1 = __float2half_rn(v.y);
    __half h2 = __float2half_rn(v.z), h3 = __float2half_rn(v.w);
    *reinterpret_cast<__half2*>(g_Xhi + i4)     = __halves2half2(h0, h1);
    *reinterpret_cast<__half2*>(g_Xhi + i4 + 2) = __halves2half2(h2, h3);
    __half l0 = __float2half_rn(v.x - __half2float(h0));
    __half l1 = __float2half_rn(v.y - __half2float(h1));
    __half l2 = __float2half_rn(v.z - __half2float(h2));
    __half l3 = __float2half_rn(v.w - __half2float(h3));
    *reinterpret_cast<__half2*>(g_Xlo + i4)     = __halves2half2(l0, l1);
    *reinterpret_cast<__half2*>(g_Xlo + i4 + 2) = __halves2half2(l2, l3);
}

// ---------------------------------------------------------------------------
// Kernel 0b: convert + transpose W -> g_Wt [n][k] fp16 hi/lo.
// ---------------------------------------------------------------------------
__global__ void convw_kernel(const float* __restrict__ Wq,
                             const float* __restrict__ Wk)
{
    int r = blockIdx.x;            // output col index (0..1023)
    int k = threadIdx.x;           // 0..255
    float v = (r < HD) ? Wq[k * HD + r] : Wk[k * HD + (r - HD)];
    __half hi = __float2half_rn(v);
    g_Wthi[r * IN_F + k] = hi;
    g_Wtlo[r * IN_F + k] = __float2half_rn(v - __half2float(hi));
}

// ---------------------------------------------------------------------------
// Kernel 1: projection GEMM via HMMA 3-term (validated R10).
// Q columns are pre-scaled by QSCALE so scores can use raw ex2.
// ---------------------------------------------------------------------------
__global__ void __launch_bounds__(256, 2)
projmma_kernel(const float* __restrict__ bq, const float* __restrict__ bk)
{
    extern __shared__ char sm[];
    const uint32_t smb = smem_u32(sm);
    __shared__ float s_bias[128];

    const int tid  = threadIdx.x;
    const int wid  = tid >> 5;
    const int lane = tid & 31;

    const int n0 = blockIdx.x * 128;   // output col tile (0..1023)
    const int m0 = blockIdx.y * 128;   // row tile
    const bool isQ = (n0 < HD);

    if (tid < 128) {
        int gc = n0 + tid;
        s_bias[tid] = isQ ? bq[gc] : bk[gc - HD];
    }

    const int m_base = (wid & 1) * 64;
    const int n_base = (wid >> 1) * 32;
    const int xr     = lane & 7;
    const int a_row  = (lane & 7) + ((lane >> 3) & 1) * 8;
    const int a_half = lane >> 4;
    const int b_row  = (lane & 7) + ((lane >> 4) ? 8 : 0);
    const int b_half = (lane >> 3) & 1;

    float acc[4][4][4];
    #pragma unroll
    for (int mi = 0; mi < 4; mi++)
        #pragma unroll
        for (int nj = 0; nj < 4; nj++)
            #pragma unroll
            for (int f = 0; f < 4; f++) acc[mi][nj][f] = 0.0f;

    for (int kk = 0; kk < 4; kk++) {           // k chunks of 64
        __syncthreads();
        #pragma unroll
        for (int it = 0; it < 4; it++) {
            int e   = tid + it * 256;
            int row = e >> 3;
            int c   = e & 7;
            uint32_t dstoff = (uint32_t)(row * 128 + ((c ^ (row & 7)) * 16));
            size_t gx = (size_t)(m0 + row) * IN_F + kk * 64 + c * 8;
            size_t gw = (size_t)(n0 + row) * IN_F + kk * 64 + c * 8;
            *reinterpret_cast<uint4*>(sm + P_AHI + dstoff) =
                *reinterpret_cast<const uint4*>(g_Xhi + gx);
            *reinterpret_cast<uint4*>(sm + P_ALO + dstoff) =
                *reinterpret_cast<const uint4*>(g_Xlo + gx);
            *reinterpret_cast<uint4*>(sm + P_BHI + dstoff) =
                *reinterpret_cast<const uint4*>(g_Wthi + gw);
            *reinterpret_cast<uint4*>(sm + P_BLO + dstoff) =
                *reinterpret_cast<const uint4*>(g_Wtlo + gw);
        }
        __syncthreads();

        const uint32_t a_off[3] = {P_AHI, P_AHI, P_ALO};
        const uint32_t b_off[3] = {P_BHI, P_BLO, P_BHI};
        #pragma unroll
        for (int t = 0; t < 3; t++) {
            const uint32_t Ab = smb + a_off[t];
            const uint32_t Bb = smb + b_off[t];
            #pragma unroll
            for (int k = 0; k < 4; k++) {
                uint32_t af[4][4];
                #pragma unroll
                for (int mi = 0; mi < 4; mi++) {
                    int row = m_base + mi * 16 + a_row;
                    ldsm_x4(af[mi], Ab + row * 128 + (((2 * k + a_half) ^ xr) * 16));
                }
                uint32_t bf[2][4];
                #pragma unroll
                for (int nb = 0; nb < 2; nb++) {
                    int row = n_base + nb * 16 + b_row;
                    ldsm_x4(bf[nb], Bb + row * 128 + (((2 * k + b_half) ^ xr) * 16));
                }
                #pragma unroll
                for (int mi = 0; mi < 4; mi++) {
                    mma16816(acc[mi][0], af[mi], bf[0][0], bf[0][1]);
                    mma16816(acc[mi][1], af[mi], bf[0][2], bf[0][3]);
                    mma16816(acc[mi][2], af[mi], bf[1][0], bf[1][1]);
                    mma16816(acc[mi][3], af[mi], bf[1][2], bf[1][3]);
                }
            }
        }
    }

    // epilogue: bias (+ QSCALE for Q) + fp16 store (half2 granularity)
    const int g = lane >> 2;
    const int q = lane & 3;
    __half* __restrict__ dstbase = isQ ? g_Q : g_K;
    const int coff = isQ ? n0 : (n0 - HD);
    const float sc = isQ ? QSCALE : 1.0f;
    #pragma unroll
    for (int mi = 0; mi < 4; mi++) {
        #pragma unroll
        for (int half_row = 0; half_row < 2; half_row++) {
            int row = m0 + m_base + mi * 16 + g + half_row * 8;
            #pragma unroll
            for (int nj = 0; nj < 4; nj++) {
                int cl = n_base + nj * 8 + 2 * q;
                float f0 = (acc[mi][nj][half_row * 2 + 0] + s_bias[cl]) * sc;
                float f1 = (acc[mi][nj][half_row * 2 + 1] + s_bias[cl + 1]) * sc;
                size_t o = (size_t)row * HD + coff + cl;
                *reinterpret_cast<__half2*>(dstbase + o) =
                    __halves2half2(__float2half_rn(f0), __float2half_rn(f1));
            }
        }
    }
}

// ---------------------------------------------------------------------------
// Kernel 2: scores pass — single-term fp16 MMA (Qscaled·K), lean epilogue:
// ex2 + cvt + staged coalesced U store.  No row sums here (moved to norm).
// ---------------------------------------------------------------------------
__global__ void __launch_bounds__(256, 2)
scores_kernel()
{
    extern __shared__ char sm[];
    const uint32_t smb = smem_u32(sm);

    const int tid  = threadIdx.x;
    const int wid  = tid >> 5;
    const int lane = tid & 31;

    const int h  = blockIdx.z;
    const int m0 = blockIdx.x * 128;
    const int n0 = blockIdx.y * 128;

    // ---- load 2 tiles (128 rows x 64 fp16 = 16 KB each), swizzled 16B chunks
    #pragma unroll
    for (int it = 0; it < 4; it++) {
        int e   = tid + it * 256;        // 0..1023
        int row = e >> 3;
        int c   = e & 7;
        uint32_t dstoff = (uint32_t)(row * 128 + ((c ^ (row & 7)) * 16));
        size_t gq = (size_t)(n0 + row) * HD + h * D + c * 8;
        size_t gk = (size_t)(m0 + row) * HD + h * D + c * 8;
        *reinterpret_cast<uint4*>(sm + A_T + dstoff) =
            *reinterpret_cast<const uint4*>(g_Q + gq);
        *reinterpret_cast<uint4*>(sm + B_T + dstoff) =
            *reinterpret_cast<const uint4*>(g_K + gk);
    }
    __syncthreads();

    const int m_base = (wid & 1) * 64;
    const int n_base = (wid >> 1) * 32;
    const int xr     = lane & 7;
    const int a_row  = (lane & 7) + ((lane >> 3) & 1) * 8;
    const int a_half = lane >> 4;
    const int b_row  = (lane & 7) + ((lane >> 4) ? 8 : 0);
    const int b_half = (lane >> 3) & 1;

    float acc[4][4][4];
    #pragma unroll
    for (int mi = 0; mi < 4; mi++)
        #pragma unroll
        for (int nj = 0; nj < 4; nj++)
            #pragma unroll
            for (int f = 0; f < 4; f++) acc[mi][nj][f] = 0.0f;

    #pragma unroll
    for (int k = 0; k < 4; k++) {
        uint32_t af[4][4];
        #pragma unroll
        for (int mi = 0; mi < 4; mi++) {
            int row = m_base + mi * 16 + a_row;
            ldsm_x4(af[mi], smb + A_T + row * 128 + (((2 * k + a_half) ^ xr) * 16));
        }
        uint32_t bf[2][4];
        #pragma unroll
        for (int nb = 0; nb < 2; nb++) {
            int row = n_base + nb * 16 + b_row;
            ldsm_x4(bf[nb], smb + B_T + row * 128 + (((2 * k + b_half) ^ xr) * 16));
        }
        #pragma unroll
        for (int mi = 0; mi < 4; mi++) {
            mma16816(acc[mi][0], af[mi], bf[0][0], bf[0][1]);
            mma16816(acc[mi][1], af[mi], bf[0][2], bf[0][3]);
            mma16816(acc[mi][2], af[mi], bf[1][0], bf[1][1]);
            mma16816(acc[mi][3], af[mi], bf[1][2], bf[1][3]);
        }
    }

    __syncthreads();   // all ldsm done -> tile smem reusable for U staging

    // ---- ex2 + stage U tile into padded smem (conflict-free half2 stores)
    const int g = lane >> 2;
    const int q = lane & 3;
    #pragma unroll
    for (int mi = 0; mi < 4; mi++) {
        int r0 = m_base + mi * 16 + g;
        char* base0 = sm + r0 * U_STRIDE;
        char* base1 = sm + (r0 + 8) * U_STRIDE;
        #pragma unroll
        for (int nj = 0; nj < 4; nj++) {
            int ch = (n_base >> 1) + nj * 4 + q;
            *reinterpret_cast<__half2*>(base0 + ch * 4) =
                __floats2half2_rn(ex2f(acc[mi][nj][0]), ex2f(acc[mi][nj][1]));
            *reinterpret_cast<__half2*>(base1 + ch * 4) =
                __floats2half2_rn(ex2f(acc[mi][nj][2]), ex2f(acc[mi][nj][3]));
        }
    }
    __syncthreads();   // U staging complete

    // ---- coalesced 16B store-out: warp covers 2 rows x 256B
    #pragma unroll
    for (int it = 0; it < 8; it++) {
        int e   = it * 256 + tid;
        int row = e >> 4;
        int ck  = e & 15;
        uint4 v = *reinterpret_cast<const uint4*>(sm + row * U_STRIDE + ck * 16);
        *reinterpret_cast<uint4*>(
            g_U + ((size_t)h * NN + n0 + row) * NN + m0 + ck * 8) = v;
    }
}

// ---------------------------------------------------------------------------
// Kernel 3: normalize + mean over heads, computing Z in-kernel.
// One block per row n.  Each thread holds its 16-col segment of all 8 heads
// in registers; per-head block reduction yields Z; then scale + write.
// ---------------------------------------------------------------------------
__global__ void __launch_bounds__(256)
norm_kernel(float* __restrict__ out)
{
    const int n    = blockIdx.x;
    const int tid  = threadIdx.x;
    const int lane = tid & 31;
    const int warp = tid >> 5;

    __shared__ float s_red[8][H];
    __shared__ float zin[H];

    const int c0 = tid * 16;
    uint4 raw[H][2];
    float hs[H];

    #pragma unroll
    for (int h = 0; h < H; h++) {
        const uint4* __restrict__ p =
            reinterpret_cast<const uint4*>(g_U + ((size_t)h * NN + n) * NN + c0);
        raw[h][0] = p[0];
        raw[h][1] = p[1];
        // fp16 tree-sum of 8 half2 -> fp32 (per-thread partial)
        const __half2* h2 = reinterpret_cast<const __half2*>(&raw[h][0]);
        __half2 t0 = __hadd2(h2[0], h2[1]);
        __half2 t1 = __hadd2(h2[2], h2[3]);
        __half2 t2 = __hadd2(h2[4], h2[5]);
        __half2 t3 = __hadd2(h2[6], h2[7]);
        __half2 u0 = __hadd2(t0, t1);
        __half2 u1 = __hadd2(t2, t3);
        float2 f = __half22float2(__hadd2(u0, u1));
        hs[h] = f.x + f.y;
    }

    // per-head block reduction
    #pragma unroll
    for (int h = 0; h < H; h++) {
        float v = hs[h];
        #pragma unroll
        for (int o = 16; o; o >>= 1) v += __shfl_xor_sync(0xffffffffu, v, o);
        if (lane == 0) s_red[warp][h] = v;
    }
    __syncthreads();
    if (tid < H) {
        float s = 0.0f;
        #pragma unroll
        for (int w = 0; w < 8; w++) s += s_red[w][tid];
        zin[tid] = (1.0f / s) * (1.0f / (float)H);
    }
    __syncthreads();

    float acc[16];
    #pragma unroll
    for (int j = 0; j < 16; j++) acc[j] = 0.0f;

    #pragma unroll
    for (int h = 0; h < H; h++) {
        const float z = zin[h];
        const __half2* h2 = reinterpret_cast<const __half2*>(&raw[h][0]);
        #pragma unroll
        for (int j = 0; j < 8; j++) {
            float2 f = __half22float2(h2[j]);
            acc[j * 2 + 0] = fmaf(f.x, z, acc[j * 2 + 0]);
            acc[j * 2 + 1] = fmaf(f.y, z, acc[j * 2 + 1]);
        }
    }

    float* __restrict__ dst = out + (size_t)n * NN + c0;
    #pragma unroll
    for (int v = 0; v < 4; v++) {
        float4 w = make_float4(acc[v * 4 + 0], acc[v * 4 + 1],
                               acc[v * 4 + 2], acc[v * 4 + 3]);
        reinterpret_cast<float4*>(dst)[v] = w;
    }
}

// ---------------------------------------------------------------------------
extern "C" void kernel_launch(void* const* d_in, const int* in_sizes, int n_in,
                              void* d_out, int out_size)
{
    const float* X  = (const float*)d_in[0];
    const float* Wq = (const float*)d_in[1];
    const float* bq = (const float*)d_in[2];
    const float* Wk = (const float*)d_in[3];
    const float* bk = (const float*)d_in[4];
    float* out = (float*)d_out;

    (void)in_sizes; (void)n_in; (void)out_size;

    cudaFuncSetAttribute(scores_kernel,
                         cudaFuncAttributeMaxDynamicSharedMemorySize, SCORES_SMEM);
    cudaFuncSetAttribute(projmma_kernel,
                         cudaFuncAttributeMaxDynamicSharedMemorySize, PROJ_SMEM);

    convx_kernel<<<(NN * IN_F) / 1024, 256>>>(X);
    convw_kernel<<<2 * HD, 256>>>(Wq, Wk);
    {
        dim3 grid(2 * HD / 128, NN / 128);
        projmma_kernel<<<grid, 256, PROJ_SMEM>>>(bq, bk);
    }
    {
        dim3 grid(NN / 128, NN / 128, H);
        scores_kernel<<<grid, 256, SCORES_SMEM>>>();
    }
    norm_kernel<<<NN, 256>>>(out);
}

// round 16
// speedup vs baseline: 2.3723x; 1.0853x over previous
#include <cuda_runtime.h>
#include <cuda_fp16.h>
#include <cstdint>
#include <math.h>

#define NN    4096
#define IN_F  256
#define H     8
#define D     64
#define HD    (H * D)          // 512
// scores use exp2: fold 0.25 * log2(e) into Q at projection time
#define QSCALE 0.36067376022224085f

// ---------------------------------------------------------------------------
// Scratch (__device__ globals: allocation-free rule)
// ---------------------------------------------------------------------------
__device__ __align__(128) __half g_Xhi[NN * IN_F];
__device__ __align__(128) __half g_Xlo[NN * IN_F];
__device__ __align__(128) __half g_Wthi[(2 * HD) * IN_F];    // [n][k], n: 0..511 Wq, 512..1023 Wk
__device__ __align__(128) __half g_Wtlo[(2 * HD) * IN_F];
__device__ __align__(128) __half g_Q[NN * HD];               // fp16 Q, pre-scaled by QSCALE
__device__ __align__(128) __half g_K[NN * HD];
__device__ __align__(128) __half g_U[(size_t)H * NN * NN];   // 256 MB exp(scores) fp16

// ---------------------------------------------------------------------------
// Warp MMA helpers (sm_80+ path — tcgen05 unavailable on compute_100 target)
// ---------------------------------------------------------------------------
__device__ __forceinline__ uint32_t smem_u32(const void* p) {
    uint32_t a;
    asm("{ .reg .u64 t; cvta.to.shared.u64 t, %1; cvt.u32.u64 %0, t; }"
        : "=r"(a) : "l"(p));
    return a;
}

__device__ __forceinline__ void ldsm_x4(uint32_t (&r)[4], uint32_t addr) {
    asm volatile("ldmatrix.sync.aligned.m8n8.x4.shared.b16 {%0,%1,%2,%3}, [%4];"
                 : "=r"(r[0]), "=r"(r[1]), "=r"(r[2]), "=r"(r[3]) : "r"(addr));
}

__device__ __forceinline__ void mma16816(float (&d)[4], const uint32_t (&a)[4],
                                         uint32_t b0, uint32_t b1) {
    asm volatile(
        "mma.sync.aligned.m16n8k16.row.col.f32.f16.f16.f32 "
        "{%0,%1,%2,%3}, {%4,%5,%6,%7}, {%8,%9}, {%0,%1,%2,%3};"
        : "+f"(d[0]), "+f"(d[1]), "+f"(d[2]), "+f"(d[3])
        : "r"(a[0]), "r"(a[1]), "r"(a[2]), "r"(a[3]), "r"(b0), "r"(b1));
}

__device__ __forceinline__ float ex2f(float x) {
    float y;
    asm("ex2.approx.ftz.f32 %0, %1;" : "=f"(y) : "f"(x));
    return y;
}

#define CP_ASYNC16(dst, src) \
    asm volatile("cp.async.cg.shared.global [%0], [%1], 16;" \
                 :: "r"(dst), "l"(src) : "memory")
#define CP_COMMIT()  asm volatile("cp.async.commit_group;" ::: "memory")
#define CP_WAIT0()   asm volatile("cp.async.wait_group 0;" ::: "memory")

// scores smem: tiles (Q 16K + K 16K) + SEPARATE U staging (no aliasing)
#define A_T   0
#define B_T   16384
#define U_STG 32768
#define U_STRIDE 272
#define SCORES_SMEM (32768 + 128 * U_STRIDE)   // 67584 -> 2 CTAs/SM
#define NTILES (H * 32 * 32)                   // 8192
#define SCORES_GRID 296                        // 2 x 148 SMs, persistent
// projmma smem: 4 tiles of 128 rows x 128B
#define P_AHI 0
#define P_ALO 16384
#define P_BHI 32768
#define P_BLO 49152
#define PROJ_SMEM 65536

// ---------------------------------------------------------------------------
// Kernel 0a: convert X -> fp16 hi/lo
// ---------------------------------------------------------------------------
__global__ void convx_kernel(const float* __restrict__ X)
{
    int i4 = (blockIdx.x * 256 + threadIdx.x) * 4;     // over NN*IN_F
    float4 v = *reinterpret_cast<const float4*>(X + i4);
    __half h0 = __float2half_rn(v.x), h1 = __float2half_rn(v.y);
    __half h2 = __float2half_rn(v.z), h3 = __float2half_rn(v.w);
    *reinterpret_cast<__half2*>(g_Xhi + i4)     = __halves2half2(h0, h1);
    *reinterpret_cast<__half2*>(g_Xhi + i4 + 2) = __halves2half2(h2, h3);
    __half l0 = __float2half_rn(v.x - __half2float(h0));
    __half l1 = __float2half_rn(v.y - __half2float(h1));
    __half l2 = __float2half_rn(v.z - __half2float(h2));
    __half l3 = __float2half_rn(v.w - __half2float(h3));
    *reinterpret_cast<__half2*>(g_Xlo + i4)     = __halves2half2(l0, l1);
    *reinterpret_cast<__half2*>(g_Xlo + i4 + 2) = __halves2half2(l2, l3);
}

// ---------------------------------------------------------------------------
// Kernel 0b: convert + transpose W -> g_Wt [n][k] fp16 hi/lo.
// ---------------------------------------------------------------------------
__global__ void convw_kernel(const float* __restrict__ Wq,
                             const float* __restrict__ Wk)
{
    int r = blockIdx.x;            // output col index (0..1023)
    int k = threadIdx.x;           // 0..255
    float v = (r < HD) ? Wq[k * HD + r] : Wk[k * HD + (r - HD)];
    __half hi = __float2half_rn(v);
    g_Wthi[r * IN_F + k] = hi;
    g_Wtlo[r * IN_F + k] = __float2half_rn(v - __half2float(hi));
}

// ---------------------------------------------------------------------------
// Kernel 1: projection GEMM via HMMA 3-term (validated R10/R15).
// ---------------------------------------------------------------------------
__global__ void __launch_bounds__(256, 2)
projmma_kernel(const float* __restrict__ bq, const float* __restrict__ bk)
{
    extern __shared__ char sm[];
    const uint32_t smb = smem_u32(sm);
    __shared__ float s_bias[128];

    const int tid  = threadIdx.x;
    const int wid  = tid >> 5;
    const int lane = tid & 31;

    const int n0 = blockIdx.x * 128;   // output col tile (0..1023)
    const int m0 = blockIdx.y * 128;   // row tile
    const bool isQ = (n0 < HD);

    if (tid < 128) {
        int gc = n0 + tid;
        s_bias[tid] = isQ ? bq[gc] : bk[gc - HD];
    }

    const int m_base = (wid & 1) * 64;
    const int n_base = (wid >> 1) * 32;
    const int xr     = lane & 7;
    const int a_row  = (lane & 7) + ((lane >> 3) & 1) * 8;
    const int a_half = lane >> 4;
    const int b_row  = (lane & 7) + ((lane >> 4) ? 8 : 0);
    const int b_half = (lane >> 3) & 1;

    float acc[4][4][4];
    #pragma unroll
    for (int mi = 0; mi < 4; mi++)
        #pragma unroll
        for (int nj = 0; nj < 4; nj++)
            #pragma unroll
            for (int f = 0; f < 4; f++) acc[mi][nj][f] = 0.0f;

    for (int kk = 0; kk < 4; kk++) {           // k chunks of 64
        __syncthreads();
        #pragma unroll
        for (int it = 0; it < 4; it++) {
            int e   = tid + it * 256;
            int row = e >> 3;
            int c   = e & 7;
            uint32_t dstoff = (uint32_t)(row * 128 + ((c ^ (row & 7)) * 16));
            size_t gx = (size_t)(m0 + row) * IN_F + kk * 64 + c * 8;
            size_t gw = (size_t)(n0 + row) * IN_F + kk * 64 + c * 8;
            *reinterpret_cast<uint4*>(sm + P_AHI + dstoff) =
                *reinterpret_cast<const uint4*>(g_Xhi + gx);
            *reinterpret_cast<uint4*>(sm + P_ALO + dstoff) =
                *reinterpret_cast<const uint4*>(g_Xlo + gx);
            *reinterpret_cast<uint4*>(sm + P_BHI + dstoff) =
                *reinterpret_cast<const uint4*>(g_Wthi + gw);
            *reinterpret_cast<uint4*>(sm + P_BLO + dstoff) =
                *reinterpret_cast<const uint4*>(g_Wtlo + gw);
        }
        __syncthreads();

        const uint32_t a_off[3] = {P_AHI, P_AHI, P_ALO};
        const uint32_t b_off[3] = {P_BHI, P_BLO, P_BHI};
        #pragma unroll
        for (int t = 0; t < 3; t++) {
            const uint32_t Ab = smb + a_off[t];
            const uint32_t Bb = smb + b_off[t];
            #pragma unroll
            for (int k = 0; k < 4; k++) {
                uint32_t af[4][4];
                #pragma unroll
                for (int mi = 0; mi < 4; mi++) {
                    int row = m_base + mi * 16 + a_row;
                    ldsm_x4(af[mi], Ab + row * 128 + (((2 * k + a_half) ^ xr) * 16));
                }
                uint32_t bf[2][4];
                #pragma unroll
                for (int nb = 0; nb < 2; nb++) {
                    int row = n_base + nb * 16 + b_row;
                    ldsm_x4(bf[nb], Bb + row * 128 + (((2 * k + b_half) ^ xr) * 16));
                }
                #pragma unroll
                for (int mi = 0; mi < 4; mi++) {
                    mma16816(acc[mi][0], af[mi], bf[0][0], bf[0][1]);
                    mma16816(acc[mi][1], af[mi], bf[0][2], bf[0][3]);
                    mma16816(acc[mi][2], af[mi], bf[1][0], bf[1][1]);
                    mma16816(acc[mi][3], af[mi], bf[1][2], bf[1][3]);
                }
            }
        }
    }

    // epilogue: bias (+ QSCALE for Q) + fp16 store (half2 granularity)
    const int g = lane >> 2;
    const int q = lane & 3;
    __half* __restrict__ dstbase = isQ ? g_Q : g_K;
    const int coff = isQ ? n0 : (n0 - HD);
    const float sc = isQ ? QSCALE : 1.0f;
    #pragma unroll
    for (int mi = 0; mi < 4; mi++) {
        #pragma unroll
        for (int half_row = 0; half_row < 2; half_row++) {
            int row = m0 + m_base + mi * 16 + g + half_row * 8;
            #pragma unroll
            for (int nj = 0; nj < 4; nj++) {
                int cl = n_base + nj * 8 + 2 * q;
                float f0 = (acc[mi][nj][half_row * 2 + 0] + s_bias[cl]) * sc;
                float f1 = (acc[mi][nj][half_row * 2 + 1] + s_bias[cl + 1]) * sc;
                size_t o = (size_t)row * HD + coff + cl;
                *reinterpret_cast<__half2*>(dstbase + o) =
                    __halves2half2(__float2half_rn(f0), __float2half_rn(f1));
            }
        }
    }
}

// ---------------------------------------------------------------------------
// Kernel 2: PERSISTENT scores pass.  296 CTAs, each loops tiles with stride.
// cp.async loads tile i+1 during tile i's store phase; staging is a separate
// smem region (one fewer sync).  MMA/ex2/store bodies = validated R15 code.
// ---------------------------------------------------------------------------
__device__ __forceinline__ void issue_tile_loads(uint32_t smb, int tid,
                                                 int h, int n0, int m0)
{
    #pragma unroll
    for (int it = 0; it < 4; it++) {
        int e   = tid + it * 256;        // 0..1023
        int row = e >> 3;
        int c   = e & 7;
        uint32_t dstoff = (uint32_t)(row * 128 + ((c ^ (row & 7)) * 16));
        size_t gq = (size_t)(n0 + row) * HD + h * D + c * 8;
        size_t gk = (size_t)(m0 + row) * HD + h * D + c * 8;
        CP_ASYNC16(smb + A_T + dstoff, (const void*)(g_Q + gq));
        CP_ASYNC16(smb + B_T + dstoff, (const void*)(g_K + gk));
    }
}

__global__ void __launch_bounds__(256, 2)
scores_kernel()
{
    extern __shared__ char sm[];
    const uint32_t smb = smem_u32(sm);

    const int tid  = threadIdx.x;
    const int wid  = tid >> 5;
    const int lane = tid & 31;

    const int m_base = (wid & 1) * 64;
    const int n_base = (wid >> 1) * 32;
    const int xr     = lane & 7;
    const int a_row  = (lane & 7) + ((lane >> 3) & 1) * 8;
    const int a_half = lane >> 4;
    const int b_row  = (lane & 7) + ((lane >> 4) ? 8 : 0);
    const int b_half = (lane >> 3) & 1;
    const int g      = lane >> 2;
    const int q      = lane & 3;

    uint32_t t = blockIdx.x;
    if (t < NTILES) {
        int h = t >> 10, rr = t & 1023;
        issue_tile_loads(smb, tid, h, (rr >> 5) << 7, (rr & 31) << 7);
        CP_COMMIT();
    }

    while (t < NTILES) {
        const int h  = t >> 10;
        const int rr = t & 1023;
        const int n0 = (rr >> 5) << 7;
        const int m0 = (rr & 31) << 7;

        CP_WAIT0();
        __syncthreads();           // tiles ready; prev iter's staging reads done

        float acc[4][4][4];
        #pragma unroll
        for (int mi = 0; mi < 4; mi++)
            #pragma unroll
            for (int nj = 0; nj < 4; nj++)
                #pragma unroll
                for (int f = 0; f < 4; f++) acc[mi][nj][f] = 0.0f;

        #pragma unroll
        for (int k = 0; k < 4; k++) {
            uint32_t af[4][4];
            #pragma unroll
            for (int mi = 0; mi < 4; mi++) {
                int row = m_base + mi * 16 + a_row;
                ldsm_x4(af[mi], smb + A_T + row * 128 + (((2 * k + a_half) ^ xr) * 16));
            }
            uint32_t bf[2][4];
            #pragma unroll
            for (int nb = 0; nb < 2; nb++) {
                int row = n_base + nb * 16 + b_row;
                ldsm_x4(bf[nb], smb + B_T + row * 128 + (((2 * k + b_half) ^ xr) * 16));
            }
            #pragma unroll
            for (int mi = 0; mi < 4; mi++) {
                mma16816(acc[mi][0], af[mi], bf[0][0], bf[0][1]);
                mma16816(acc[mi][1], af[mi], bf[0][2], bf[0][3]);
                mma16816(acc[mi][2], af[mi], bf[1][0], bf[1][1]);
                mma16816(acc[mi][3], af[mi], bf[1][2], bf[1][3]);
            }
        }

        // ---- ex2 + stage into SEPARATE staging region (no sync needed first)
        #pragma unroll
        for (int mi = 0; mi < 4; mi++) {
            int r0 = m_base + mi * 16 + g;
            char* base0 = sm + U_STG + r0 * U_STRIDE;
            char* base1 = sm + U_STG + (r0 + 8) * U_STRIDE;
            #pragma unroll
            for (int nj = 0; nj < 4; nj++) {
                int ch = (n_base >> 1) + nj * 4 + q;
                *reinterpret_cast<__half2*>(base0 + ch * 4) =
                    __floats2half2_rn(ex2f(acc[mi][nj][0]), ex2f(acc[mi][nj][1]));
                *reinterpret_cast<__half2*>(base1 + ch * 4) =
                    __floats2half2_rn(ex2f(acc[mi][nj][2]), ex2f(acc[mi][nj][3]));
            }
        }
        __syncthreads();           // staging complete; all ldsm of tiles done

        // ---- prefetch next tile into tile region (overlaps store-out below)
        uint32_t tn = t + SCORES_GRID;
        if (tn < NTILES) {
            int h2 = tn >> 10, rr2 = tn & 1023;
            issue_tile_loads(smb, tid, h2, (rr2 >> 5) << 7, (rr2 & 31) << 7);
            CP_COMMIT();
        }

        // ---- coalesced 16B store-out: warp covers 2 rows x 256B
        #pragma unroll
        for (int it = 0; it < 8; it++) {
            int e   = it * 256 + tid;
            int row = e >> 4;
            int ck  = e & 15;
            uint4 v = *reinterpret_cast<const uint4*>(
                sm + U_STG + row * U_STRIDE + ck * 16);
            *reinterpret_cast<uint4*>(
                g_U + ((size_t)h * NN + n0 + row) * NN + m0 + ck * 8) = v;
        }

        t = tn;
    }
}

// ---------------------------------------------------------------------------
// Kernel 3: normalize + mean over heads, computing Z in-kernel (validated R15).
// ---------------------------------------------------------------------------
__global__ void __launch_bounds__(256)
norm_kernel(float* __restrict__ out)
{
    const int n    = blockIdx.x;
    const int tid  = threadIdx.x;
    const int lane = tid & 31;
    const int warp = tid >> 5;

    __shared__ float s_red[8][H];
    __shared__ float zin[H];

    const int c0 = tid * 16;
    uint4 raw[H][2];
    float hs[H];

    #pragma unroll
    for (int h = 0; h < H; h++) {
        const uint4* __restrict__ p =
            reinterpret_cast<const uint4*>(g_U + ((size_t)h * NN + n) * NN + c0);
        raw[h][0] = p[0];
        raw[h][1] = p[1];
        const __half2* h2 = reinterpret_cast<const __half2*>(&raw[h][0]);
        __half2 t0 = __hadd2(h2[0], h2[1]);
        __half2 t1 = __hadd2(h2[2], h2[3]);
        __half2 t2 = __hadd2(h2[4], h2[5]);
        __half2 t3 = __hadd2(h2[6], h2[7]);
        __half2 u0 = __hadd2(t0, t1);
        __half2 u1 = __hadd2(t2, t3);
        float2 f = __half22float2(__hadd2(u0, u1));
        hs[h] = f.x + f.y;
    }

    #pragma unroll
    for (int h = 0; h < H; h++) {
        float v = hs[h];
        #pragma unroll
        for (int o = 16; o; o >>= 1) v += __shfl_xor_sync(0xffffffffu, v, o);
        if (lane == 0) s_red[warp][h] = v;
    }
    __syncthreads();
    if (tid < H) {
        float s = 0.0f;
        #pragma unroll
        for (int w = 0; w < 8; w++) s += s_red[w][tid];
        zin[tid] = (1.0f / s) * (1.0f / (float)H);
    }
    __syncthreads();

    float acc[16];
    #pragma unroll
    for (int j = 0; j < 16; j++) acc[j] = 0.0f;

    #pragma unroll
    for (int h = 0; h < H; h++) {
        const float z = zin[h];
        const __half2* h2 = reinterpret_cast<const __half2*>(&raw[h][0]);
        #pragma unroll
        for (int j = 0; j < 8; j++) {
            float2 f = __half22float2(h2[j]);
            acc[j * 2 + 0] = fmaf(f.x, z, acc[j * 2 + 0]);
            acc[j * 2 + 1] = fmaf(f.y, z, acc[j * 2 + 1]);
        }
    }

    float* __restrict__ dst = out + (size_t)n * NN + c0;
    #pragma unroll
    for (int v = 0; v < 4; v++) {
        float4 w = make_float4(acc[v * 4 + 0], acc[v * 4 + 1],
                               acc[v * 4 + 2], acc[v * 4 + 3]);
        reinterpret_cast<float4*>(dst)[v] = w;
    }
}

// ---------------------------------------------------------------------------
extern "C" void kernel_launch(void* const* d_in, const int* in_sizes, int n_in,
                              void* d_out, int out_size)
{
    const float* X  = (const float*)d_in[0];
    const float* Wq = (const float*)d_in[1];
    const float* bq = (const float*)d_in[2];
    const float* Wk = (const float*)d_in[3];
    const float* bk = (const float*)d_in[4];
    float* out = (float*)d_out;

    (void)in_sizes; (void)n_in; (void)out_size;

    cudaFuncSetAttribute(scores_kernel,
                         cudaFuncAttributeMaxDynamicSharedMemorySize, SCORES_SMEM);
    cudaFuncSetAttribute(projmma_kernel,
                         cudaFuncAttributeMaxDynamicSharedMemorySize, PROJ_SMEM);

    convx_kernel<<<(NN * IN_F) / 1024, 256>>>(X);
    convw_kernel<<<2 * HD, 256>>>(Wq, Wk);
    {
        dim3 grid(2 * HD / 128, NN / 128);
        projmma_kernel<<<grid, 256, PROJ_SMEM>>>(bq, bk);
    }
    scores_kernel<<<SCORES_GRID, 256, SCORES_SMEM>>>();
    norm_kernel<<<NN, 256>>>(out);
}